// round 12
// baseline (speedup 1.0000x reference)
#include <cuda_runtime.h>
#include <cuda_bf16.h>
#include <cuda_fp16.h>
#include <cstdint>

#define Tt   1024
#define DIMD 1024
#define Hh   8
#define Ee   5
#define KK   3
#define BT   2048
#define HS   512
#define HE   40
#define QSCALE 0.125f

#define N1 3840
#define N2 1024
#define V2 2560

// ---------------- scratch ----------------------------------------------------
__device__ float g_C1 [BT * N1];
// fp16 blob for gemm1: A(hi,lo), B(hi) all rows, B(lo) used for SsSd tile
#define A1Hf 0
#define A1Lf (BT * 1024)
#define B1Hf (2 * BT * 1024)
#define B1Lf (2 * BT * 1024 + N1 * 1024)
__device__ __half g_W1f[2 * BT * 1024 + 2 * N1 * 1024];
// fp16 blob for gemm2
#define A2H 0
#define A2L (BT * V2)
#define B2H (2 * BT * V2)
__device__ __half g_W2[2 * BT * V2 + N2 * V2];

__device__ float g_sdg[BT * HE];
// attention operands: packed fp16x2 pairs
__device__ uint32_t g_Qh[16 * 1024 * 32];   // [bh][t][dpair]
__device__ uint32_t g_Ql[16 * 1024 * 32];
__device__ uint32_t g_Kh[16 * 1024 * 32];   // single-rounded fp16
__device__ uint32_t g_Vh[16 * 64 * 512];    // [bh][d][tpair], single-rounded fp16

// ---------------- helpers -----------------------------------------------------
__device__ __forceinline__ uint32_t smem_u32(const void* p) {
    uint32_t a;
    asm("{ .reg .u64 t; cvta.to.shared.u64 t, %1; cvt.u32.u64 %0, t; }" : "=r"(a) : "l"(p));
    return a;
}
__device__ __forceinline__ void cpasync16(uint32_t dst, const void* src) {
    asm volatile("cp.async.cg.shared.global [%0], [%1], 16;\n" :: "r"(dst), "l"(src));
}
__device__ __forceinline__ void cp_commit() { asm volatile("cp.async.commit_group;\n"); }
template<int N> __device__ __forceinline__ void cp_wait() { asm volatile("cp.async.wait_group %0;\n" :: "n"(N)); }

__device__ __forceinline__ void mma16816f(float* c, const uint32_t* a, const uint32_t* b) {
    asm volatile(
        "mma.sync.aligned.m16n8k16.row.col.f32.f16.f16.f32 "
        "{%0,%1,%2,%3}, {%4,%5,%6,%7}, {%8,%9}, {%0,%1,%2,%3};"
        : "+f"(c[0]), "+f"(c[1]), "+f"(c[2]), "+f"(c[3])
        : "r"(a[0]), "r"(a[1]), "r"(a[2]), "r"(a[3]), "r"(b[0]), "r"(b[1]));
}
__device__ __forceinline__ void ldm_x4(uint32_t* r, uint32_t addr) {
    asm volatile("ldmatrix.sync.aligned.m8n8.x4.shared.b16 {%0,%1,%2,%3}, [%4];"
        : "=r"(r[0]), "=r"(r[1]), "=r"(r[2]), "=r"(r[3]) : "r"(addr));
}
__device__ __forceinline__ uint32_t packh2(float lo, float hi) {
    __half2 h = __floats2half2_rn(lo, hi);
    return *(uint32_t*)&h;
}
__device__ __forceinline__ uint32_t packh2res(uint32_t p, float lo, float hi) {
    __half2 ph = *(__half2*)&p;
    float2 bk = __half22float2(ph);
    return packh2(lo - bk.x, hi - bk.y);
}
#define WGBAR(id) asm volatile("bar.sync %0, 128;" :: "r"((id) + 1) : "memory")

// ---------------- fp16 GEMM: C = Ah@Bh^T + Al@Bh^T (+ Ah@Bl^T if TERM3) ------
// FUSEQK: tiles with n0<1024 write fp16 Q(split)/K(rounded) pair arrays.
template<int NT, int KTOT, bool FUSEQK, bool TERM3>
__device__ __forceinline__ void gemmf_body(const char* __restrict__ W,
                                           uint32_t offAh, uint32_t offAl,
                                           uint32_t offBh, uint32_t offBl,
                                           float* __restrict__ C, int Ntot)
{
    constexpr int ROWS  = 256 + (TERM3 ? 2 : 1) * NT;
    constexpr int STAGE = ROWS * 64;
    constexpr int NSTEP = KTOT / 32;
    constexpr int NTW   = NT / 2;
    constexpr int NPAIR = NTW / 16;
    constexpr int NA    = NTW / 8;
    constexpr int CPT   = ROWS / 64;
    constexpr int NB    = NT / 64;
    constexpr size_t K2B = KTOT * 2;

    extern __shared__ char sm_raw[];
    const uint32_t sb = smem_u32(sm_raw);
    const int tid = threadIdx.x, wid = tid >> 5, lane = tid & 31;
    const int wm = wid & 3, wn = wid >> 2;
    const int m0 = blockIdx.y * 128, n0 = blockIdx.x * NT;

    const int r0 = tid >> 2;
    const int cc = (tid & 3) * 16;
    const uint32_t dst0 = r0 * 64 + (cc ^ (((r0 >> 1) & 3) * 16));
    const char* pAh = W + offAh + (size_t)(m0 + r0) * K2B + cc;
    const char* pAl = W + offAl + (size_t)(m0 + r0) * K2B + cc;
    const char* pBh = W + offBh + (size_t)(n0 + r0) * K2B + cc;
    const char* pBl = W + offBl + (size_t)(n0 + r0) * K2B + cc;

    auto issue = [&](int kt, int slot) {
        const uint32_t st = sb + slot * STAGE + dst0;
        const size_t gk = (size_t)kt * 64;
#pragma unroll
        for (int i = 0; i < CPT; i++) {
            const char* src;
            if      (i < 2)      src = pAh + (size_t)i * (64 * K2B);
            else if (i < 4)      src = pAl + (size_t)(i - 2) * (64 * K2B);
            else if (i < 4 + NB) src = pBh + (size_t)(i - 4) * (64 * K2B);
            else                 src = pBl + (size_t)(i - 4 - NB) * (64 * K2B);
            cpasync16(st + i * 4096, src + gk);
        }
    };

    const uint32_t ahi = (lane >> 4) * 16;
    const uint32_t bhi = ((lane >> 3) & 1) * 16;
    uint32_t aof[2], aswz[2], bof[NPAIR], bswz[NPAIR];
#pragma unroll
    for (int mi = 0; mi < 2; mi++) {
        int r = wm * 32 + mi * 16 + (lane & 15);
        aof[mi] = r * 64; aswz[mi] = ((r >> 1) & 3) * 16;
    }
#pragma unroll
    for (int pj = 0; pj < NPAIR; pj++) {
        int r = wn * NTW + pj * 16 + ((lane >> 4) << 3) + (lane & 7);
        bof[pj] = (256 + r) * 64; bswz[pj] = ((r >> 1) & 3) * 16;
    }

    float acc[2][NA][4];
#pragma unroll
    for (int mi = 0; mi < 2; mi++)
#pragma unroll
        for (int na = 0; na < NA; na++)
#pragma unroll
            for (int q = 0; q < 4; q++) acc[mi][na][q] = 0.f;

    issue(0, 0); cp_commit();
    issue(1, 1); cp_commit();

    for (int kt = 0; kt < NSTEP; kt++) {
        if (kt + 1 < NSTEP) cp_wait<1>(); else cp_wait<0>();
        __syncthreads();
        if (kt + 2 < NSTEP) { issue(kt + 2, (kt + 2) % 3); cp_commit(); }

        uint32_t stg = sb + (kt % 3) * STAGE;
#pragma unroll
        for (int ks = 0; ks < 2; ks++) {
            const uint32_t ca = (uint32_t)ks * 32 + ahi;
            const uint32_t cb = (uint32_t)ks * 32 + bhi;
            uint32_t ah[2][4], al[2][4];
            ldm_x4(ah[0], stg + aof[0] + (ca ^ aswz[0]));
            ldm_x4(ah[1], stg + aof[1] + (ca ^ aswz[1]));
            ldm_x4(al[0], stg + 8192 + aof[0] + (ca ^ aswz[0]));
            ldm_x4(al[1], stg + 8192 + aof[1] + (ca ^ aswz[1]));
#pragma unroll
            for (int ph = 0; ph < NPAIR; ph += 2) {
                uint32_t bb[2][4];
                ldm_x4(bb[0], stg + bof[ph]     + (cb ^ bswz[ph]));
                ldm_x4(bb[1], stg + bof[ph + 1] + (cb ^ bswz[ph + 1]));
#pragma unroll
                for (int mi = 0; mi < 2; mi++) {
                    mma16816f(acc[mi][2*ph],     ah[mi], &bb[0][0]);
                    mma16816f(acc[mi][2*ph+1],   ah[mi], &bb[0][2]);
                    mma16816f(acc[mi][2*ph+2],   ah[mi], &bb[1][0]);
                    mma16816f(acc[mi][2*ph+3],   ah[mi], &bb[1][2]);
                }
#pragma unroll
                for (int mi = 0; mi < 2; mi++) {
                    mma16816f(acc[mi][2*ph],     al[mi], &bb[0][0]);
                    mma16816f(acc[mi][2*ph+1],   al[mi], &bb[0][2]);
                    mma16816f(acc[mi][2*ph+2],   al[mi], &bb[1][0]);
                    mma16816f(acc[mi][2*ph+3],   al[mi], &bb[1][2]);
                }
                if (TERM3) {
                    ldm_x4(bb[0], stg + bof[ph]     + NT * 64 + (cb ^ bswz[ph]));
                    ldm_x4(bb[1], stg + bof[ph + 1] + NT * 64 + (cb ^ bswz[ph + 1]));
#pragma unroll
                    for (int mi = 0; mi < 2; mi++) {
                        mma16816f(acc[mi][2*ph],     ah[mi], &bb[0][0]);
                        mma16816f(acc[mi][2*ph+1],   ah[mi], &bb[0][2]);
                        mma16816f(acc[mi][2*ph+2],   ah[mi], &bb[1][0]);
                        mma16816f(acc[mi][2*ph+3],   ah[mi], &bb[1][2]);
                    }
                }
            }
        }
    }

    const int g  = lane >> 2;
    const int tg = lane & 3;

    if (FUSEQK && n0 < 1024) {
        const bool isQ = (n0 < 512);
        const float sc = isQ ? QSCALE : 1.0f;
#pragma unroll
        for (int mi = 0; mi < 2; mi++) {
            int r = m0 + wm * 32 + mi * 16 + g;
            int b_ = r >> 10, t = r & 1023;
#pragma unroll
            for (int na = 0; na < NA; na++) {
                int ccc = n0 + wn * NTW + na * 8 + tg * 2;
                int h = (ccc >> 6) & 7;
                int p = (ccc & 63) >> 1;
                size_t base = (((size_t)(b_ * 8 + h) << 10) + t) * 32 + p;
                float v0 = acc[mi][na][0] * sc, v1 = acc[mi][na][1] * sc;
                float w0 = acc[mi][na][2] * sc, w1 = acc[mi][na][3] * sc;
                uint32_t h0 = packh2(v0, v1);
                uint32_t h1 = packh2(w0, w1);
                if (isQ) {
                    g_Qh[base] = h0; g_Ql[base] = packh2res(h0, v0, v1);
                    g_Qh[base + 8 * 32] = h1; g_Ql[base + 8 * 32] = packh2res(h1, w0, w1);
                } else {
                    g_Kh[base] = h0;
                    g_Kh[base + 8 * 32] = h1;
                }
            }
        }
    } else {
#pragma unroll
        for (int mi = 0; mi < 2; mi++) {
            int r = m0 + wm * 32 + mi * 16 + g;
#pragma unroll
            for (int na = 0; na < NA; na++) {
                int ccc = n0 + wn * NTW + na * 8 + tg * 2;
                *(float2*)(C + (size_t)r * Ntot + ccc)       = make_float2(acc[mi][na][0], acc[mi][na][1]);
                *(float2*)(C + (size_t)(r + 8) * Ntot + ccc) = make_float2(acc[mi][na][2], acc[mi][na][3]);
            }
        }
    }
}

#define GEMM1_SMEM (3 * 512 * 64)   // 98304 (covers TERM3 NT=128; 2-term uses 73728)
#define GEMM2_SMEM (3 * 320 * 64)   // 61440 (NT=64 2-term)

__global__ __launch_bounds__(256, 2)
void gemm1() {
    if (blockIdx.x < 8)        // Q (0-3) + K (4-7) tiles, fused epilogue
        gemmf_body<128, 1024, true,  false>((const char*)g_W1f, A1Hf*2, A1Lf*2, B1Hf*2, B1Lf*2, g_C1, N1);
    else if (blockIdx.x < 28)  // V tiles
        gemmf_body<128, 1024, false, false>((const char*)g_W1f, A1Hf*2, A1Lf*2, B1Hf*2, B1Lf*2, g_C1, N1);
    else                       // SsSd tile: fp16 3-term (near-fp32 accuracy)
        gemmf_body<128, 1024, false, true >((const char*)g_W1f, A1Hf*2, A1Lf*2, B1Hf*2, B1Lf*2, g_C1, N1);
}
__global__ __launch_bounds__(256, 3)
void gemm2(float* __restrict__ out) {
    gemmf_body<64, 2560, false, false>((const char*)g_W2, A2H*2, A2L*2, B2H*2, 0, out, N2);
}

// ---------------- prep kernels ----------------------------------------------
__global__ __launch_bounds__(256) void prep_a1(const float* __restrict__ x) {
    int gid = blockIdx.x * 256 + threadIdx.x;
    float v = x[gid];
    __half fh = __float2half_rn(v);
    __half fl = __float2half_rn(v - __half2float(fh));
    g_W1f[A1Hf + gid] = fh;
    g_W1f[A1Lf + gid] = fl;
}

__global__ void prep_b1(const float* __restrict__ Wq, const float* __restrict__ Wk,
                        const float* __restrict__ Wv, const float* __restrict__ Ws,
                        const float* __restrict__ Wd)
{
    __shared__ float tile[32][33];
    int k0 = blockIdx.x * 32;
    int n0 = blockIdx.y * 32;
    int tx = threadIdx.x, ty = threadIdx.y;
#pragma unroll
    for (int yy = 0; yy < 32; yy += 8) {
        int k = k0 + ty + yy, n = n0 + tx;
        float w;
        if      (n < 512)  w = Wq[(size_t)k * 512  + n];
        else if (n < 1024) w = Wk[(size_t)k * 512  + n - 512];
        else if (n < 3584) w = Wv[(size_t)k * 2560 + n - 1024];
        else if (n < 3624) w = Ws[(size_t)k * 40   + n - 3584];
        else if (n < 3664) w = Wd[(size_t)k * 40   + n - 3624];
        else               w = 0.f;
        tile[ty + yy][tx] = w;
    }
    __syncthreads();
#pragma unroll
    for (int yy = 0; yy < 32; yy += 8) {
        int n = n0 + ty + yy, k = k0 + tx;
        float w = tile[tx][ty + yy];
        int idx = n * 1024 + k;
        __half fh = __float2half_rn(w);
        g_W1f[B1Hf + idx] = fh;
        if (n >= 3584)   // Bl only consumed by the SsSd 3-term tile
            g_W1f[B1Lf + idx] = __float2half_rn(w - __half2float(fh));
    }
}

__global__ __launch_bounds__(256) void prep_b2(const float* __restrict__ Wo) {
    int gid = blockIdx.x * 256 + threadIdx.x;
    int he = gid >> 16;
    int d  = (gid >> 6) & 1023;
    int c  = gid & 63;
    g_W2[B2H + d * V2 + he * 64 + c] = __float2half_rn(Wo[gid]);
}

// ---------------- fused routing gates + expert V mix + transposed pack -------
__global__ __launch_bounds__(256) void route_pack() {
    __shared__ uint32_t tvh[4][65];
    int gid = blockIdx.x * 256 + threadIdx.x;
    int d  = gid & 63;
    int kp = (gid >> 6) & 511;
    int bh = gid >> 15;
    int b = bh >> 3, h = bh & 7;

    float v[2];
#pragma unroll
    for (int u = 0; u < 2; u++) {
        int t = kp * 2 + u;
        const float* row = g_C1 + (size_t)(b * 1024 + t) * N1;
        const float* sl = row + 3584 + h * Ee;
        float s[Ee];
#pragma unroll
        for (int e = 0; e < Ee; e++) s[e] = sl[e];
        float acc = 0.f;
#pragma unroll
        for (int e = 0; e < Ee; e++) {
            int rank = 0;
#pragma unroll
            for (int j = 0; j < Ee; j++)
                rank += (s[j] > s[e]) || (s[j] == s[e] && j < e);
            float gate = (rank < KK) ? 1.0f / (1.0f + expf(-s[e])) : 0.f;
            acc = fmaf(gate, row[1024 + (h * Ee + e) * 64 + d], acc);
        }
        v[u] = acc;

        if (d < Ee) {
            const float* dl = row + 3624 + h * Ee;
            float tq[Ee];
#pragma unroll
            for (int e = 0; e < Ee; e++) tq[e] = dl[e];
            int e = d, rank = 0;
#pragma unroll
            for (int j = 0; j < Ee; j++)
                rank += (tq[j] > tq[e]) || (tq[j] == tq[e] && j < e);
            g_sdg[(b * 1024 + t) * HE + h * Ee + e] = (rank < KK) ? 1.f : 0.f;
        }
    }
    tvh[kp & 3][d] = packh2(v[0], v[1]);
    __syncthreads();
    int td  = threadIdx.x >> 2;
    int tk4 = threadIdx.x & 3;
    int kp0 = (blockIdx.x * 4) & 511;
    g_Vh[((size_t)bh * 64 + td) * 512 + kp0 + tk4] = tvh[tk4][td];
}

// ---------------- tensor-core causal flash attention (fp16 2-term) -----------
#define AQS   (64 * 36)
#define ATL   (64 * 36)
#define ASTG  (2 * ATL)
#define AWG_U (2 * AQS + 2 * ASTG)
#define ATTN_SMEM (2 * AWG_U * 4)

__global__ __launch_bounds__(256) void attn_tc() {
    extern __shared__ uint32_t sm[];
    const int bh   = blockIdx.y;
    const int b    = bh >> 3, h = bh & 7;
    const int wg   = threadIdx.x >> 7;
    const int qt   = wg ? (15 - blockIdx.x) : blockIdx.x;
    const int tid  = threadIdx.x & 127;
    const int w    = tid >> 5;
    const int lane = tid & 31;
    const int g    = lane >> 2;
    const int tig  = lane & 3;
    uint32_t* smg  = sm + wg * AWG_U;
    const uint32_t sb = smem_u32(smg);

    auto issue = [&](int kt, int s) {
#pragma unroll
        for (int i = 0; i < 8; i++) {
            int a = i >> 2;
            int r = (i & 3) * 16 + (tid >> 3);
            int c = tid & 7;
            uint32_t dst = sb + (2 * AQS + s * ASTG + a * ATL + r * 36) * 4 + c * 16;
            const uint32_t* srcb;
            if (a == 0) srcb = g_Kh + ((size_t)(bh << 10) + kt * 64 + r) * 32;
            else        srcb = g_Vh + ((size_t)bh * 64 + r) * 512 + kt * 32;
            cpasync16(dst, (const char*)srcb + c * 16);
        }
    };
    issue(0, 0); cp_commit();

    {
        const uint32_t* qhsrc = g_Qh + ((size_t)(bh << 10) + qt * 64) * 32;
        const uint32_t* qlsrc = g_Ql + ((size_t)(bh << 10) + qt * 64) * 32;
#pragma unroll
        for (int j = 0; j < 4; j++) {
            int idx = tid + j * 128;
            int row = idx >> 3, po = (idx & 7) * 4;
            *(uint4*)&smg[row * 36 + po]       = *(const uint4*)(qhsrc + row * 32 + po);
            *(uint4*)&smg[AQS + row * 36 + po] = *(const uint4*)(qlsrc + row * 32 + po);
        }
    }
    WGBAR(wg);

    uint32_t qa[2][4][4];
#pragma unroll
    for (int hl = 0; hl < 2; hl++) {
        int qb = hl * AQS;
#pragma unroll
        for (int kb = 0; kb < 4; kb++) {
            qa[hl][kb][0] = smg[qb + (w * 16 + g)     * 36 + kb * 8 + tig];
            qa[hl][kb][1] = smg[qb + (w * 16 + g + 8) * 36 + kb * 8 + tig];
            qa[hl][kb][2] = smg[qb + (w * 16 + g)     * 36 + kb * 8 + 4 + tig];
            qa[hl][kb][3] = smg[qb + (w * 16 + g + 8) * 36 + kb * 8 + 4 + tig];
        }
    }

    const int li   = lane >> 3;
    const uint32_t lbase = (((li >> 1) * 8 + (lane & 7)) * 36 + (li & 1) * 4) * 4;

    float o[8][4];
#pragma unroll
    for (int a = 0; a < 8; a++)
#pragma unroll
        for (int q = 0; q < 4; q++) o[a][q] = 0.f;
    float m[2] = {-1e30f, -1e30f}, l[2] = {0.f, 0.f};

    for (int kt = 0; kt <= qt; kt++) {
        if (kt < qt) { issue(kt + 1, (kt + 1) & 1); cp_commit(); cp_wait<1>(); }
        else         { cp_wait<0>(); }
        WGBAR(wg);

        const uint32_t su  = sb + (2 * AQS + (kt & 1) * ASTG) * 4;
        const uint32_t Khb = su, Vhb = su + ATL * 4;

        float s[8][4];
#pragma unroll
        for (int a = 0; a < 8; a++)
#pragma unroll
            for (int q = 0; q < 4; q++) s[a][q] = 0.f;

#pragma unroll
        for (int kb = 0; kb < 4; kb++) {
            uint32_t bb[4][4];
#pragma unroll
            for (int j = 0; j < 4; j++)
                ldm_x4(bb[j], Khb + lbase + (j * 576 + kb * 8) * 4);
#pragma unroll
            for (int j = 0; j < 4; j++) {
                mma16816f(s[2*j],   qa[0][kb], &bb[j][0]);
                mma16816f(s[2*j+1], qa[0][kb], &bb[j][2]);
            }
#pragma unroll
            for (int j = 0; j < 4; j++) {
                mma16816f(s[2*j],   qa[1][kb], &bb[j][0]);
                mma16816f(s[2*j+1], qa[1][kb], &bb[j][2]);
            }
        }

        if (kt == qt) {
            int r0 = w * 16 + g;
#pragma unroll
            for (int na = 0; na < 8; na++) {
                int c0 = na * 8 + 2 * tig;
                if (c0     > r0)     s[na][0] = -1e9f;
                if (c0 + 1 > r0)     s[na][1] = -1e9f;
                if (c0     > r0 + 8) s[na][2] = -1e9f;
                if (c0 + 1 > r0 + 8) s[na][3] = -1e9f;
            }
        }

#pragma unroll
        for (int ri = 0; ri < 2; ri++) {
            float mx = -1e30f;
#pragma unroll
            for (int a = 0; a < 8; a++)
                mx = fmaxf(mx, fmaxf(s[a][2 * ri], s[a][2 * ri + 1]));
            mx = fmaxf(mx, __shfl_xor_sync(0xffffffffu, mx, 1));
            mx = fmaxf(mx, __shfl_xor_sync(0xffffffffu, mx, 2));
            float mnew = fmaxf(m[ri], mx);
            float corr = __expf(m[ri] - mnew);
            float rs = 0.f;
#pragma unroll
            for (int a = 0; a < 8; a++) {
                float p0 = __expf(s[a][2 * ri]     - mnew);
                float p1 = __expf(s[a][2 * ri + 1] - mnew);
                s[a][2 * ri] = p0; s[a][2 * ri + 1] = p1;
                rs += p0 + p1;
            }
            rs += __shfl_xor_sync(0xffffffffu, rs, 1);
            rs += __shfl_xor_sync(0xffffffffu, rs, 2);
            l[ri] = l[ri] * corr + rs;
            m[ri] = mnew;
#pragma unroll
            for (int a = 0; a < 8; a++) { o[a][2 * ri] *= corr; o[a][2 * ri + 1] *= corr; }
        }

#pragma unroll
        for (int kb = 0; kb < 4; kb++) {
            uint32_t ph[4], pl[4];
            ph[0] = packh2(s[2*kb][0],   s[2*kb][1]);
            ph[1] = packh2(s[2*kb][2],   s[2*kb][3]);
            ph[2] = packh2(s[2*kb+1][0], s[2*kb+1][1]);
            ph[3] = packh2(s[2*kb+1][2], s[2*kb+1][3]);
            pl[0] = packh2res(ph[0], s[2*kb][0],   s[2*kb][1]);
            pl[1] = packh2res(ph[1], s[2*kb][2],   s[2*kb][3]);
            pl[2] = packh2res(ph[2], s[2*kb+1][0], s[2*kb+1][1]);
            pl[3] = packh2res(ph[3], s[2*kb+1][2], s[2*kb+1][3]);

            uint32_t bb[4][4];
#pragma unroll
            for (int j = 0; j < 4; j++)
                ldm_x4(bb[j], Vhb + lbase + (j * 576 + kb * 8) * 4);
#pragma unroll
            for (int j = 0; j < 4; j++) {
                mma16816f(o[2*j],   ph, &bb[j][0]);
                mma16816f(o[2*j+1], ph, &bb[j][2]);
            }
#pragma unroll
            for (int j = 0; j < 4; j++) {
                mma16816f(o[2*j],   pl, &bb[j][0]);
                mma16816f(o[2*j+1], pl, &bb[j][2]);
            }
        }
        WGBAR(wg);
    }

    // ---- fused epilogue: A2 = fp16-split(sd * O) for all 5 experts ----
    float inv0 = 1.0f / l[0], inv1 = 1.0f / l[1];
    int row0 = qt * 64 + w * 16 + g;
    int bt0  = b * 1024 + row0;

    float g0[Ee], g1[Ee];
#pragma unroll
    for (int e = 0; e < Ee; e++) {
        g0[e] = g_sdg[bt0 * HE + h * Ee + e];
        g1[e] = g_sdg[(bt0 + 8) * HE + h * Ee + e];
    }
    uint32_t* a2h0 = (uint32_t*)(g_W2 + A2H + (size_t)bt0 * V2);
    uint32_t* a2l0 = (uint32_t*)(g_W2 + A2L + (size_t)bt0 * V2);
    uint32_t* a2h1 = (uint32_t*)(g_W2 + A2H + (size_t)(bt0 + 8) * V2);
    uint32_t* a2l1 = (uint32_t*)(g_W2 + A2L + (size_t)(bt0 + 8) * V2);

#pragma unroll
    for (int na = 0; na < 8; na++) {
        int c0 = na * 8 + 2 * tig;
        float v00 = o[na][0] * inv0, v01 = o[na][1] * inv0;
        float v10 = o[na][2] * inv1, v11 = o[na][3] * inv1;
        uint32_t h0u = packh2(v00, v01), l0u = packh2res(h0u, v00, v01);
        uint32_t h1u = packh2(v10, v11), l1u = packh2res(h1u, v10, v11);
#pragma unroll
        for (int e = 0; e < Ee; e++) {
            int cw = ((h * Ee + e) * 64 + c0) >> 1;
            a2h0[cw] = (g0[e] != 0.f) ? h0u : 0u;
            a2l0[cw] = (g0[e] != 0.f) ? l0u : 0u;
            a2h1[cw] = (g1[e] != 0.f) ? h1u : 0u;
            a2l1[cw] = (g1[e] != 0.f) ? l1u : 0u;
        }
    }
}

// ---------------- launch ------------------------------------------------------
extern "C" void kernel_launch(void* const* d_in, const int* in_sizes, int n_in,
                              void* d_out, int out_size)
{
    const float* x  = (const float*)d_in[0];
    const float* Wq = (const float*)d_in[1];
    const float* Wk = (const float*)d_in[2];
    const float* Wv = (const float*)d_in[3];
    const float* Ws = (const float*)d_in[4];
    const float* Wd = (const float*)d_in[5];
    const float* Wo = (const float*)d_in[6];
    float* out = (float*)d_out;

    cudaFuncSetAttribute(gemm1,   cudaFuncAttributeMaxDynamicSharedMemorySize, GEMM1_SMEM);
    cudaFuncSetAttribute(gemm2,   cudaFuncAttributeMaxDynamicSharedMemorySize, GEMM2_SMEM);
    cudaFuncSetAttribute(attn_tc, cudaFuncAttributeMaxDynamicSharedMemorySize, ATTN_SMEM);

    prep_a1   <<<BT * DIMD / 256, 256>>>(x);
    prep_b1   <<<dim3(32, 120), dim3(32, 8)>>>(Wq, Wk, Wv, Ws, Wd);
    prep_b2   <<<HE * DIMD * 64 / 256, 256>>>(Wo);
    gemm1     <<<dim3(29, 16), 256, GEMM1_SMEM>>>();
    route_pack<<<16 * 512 * 64 / 256, 256>>>();
    attn_tc   <<<dim3(8, 16), 256, ATTN_SMEM>>>();
    gemm2     <<<dim3(N2 / 64, BT / 128), 256, GEMM2_SMEM>>>(out);
}

// round 13
// speedup vs baseline: 1.2372x; 1.2372x over previous
#include <cuda_runtime.h>
#include <cuda_fp16.h>
#include <cstdint>

#define Tt   1024
#define DIMD 1024
#define Hh   8
#define Ee   5
#define KK   3
#define BT   2048
#define HS   512
#define HE   40
#define QSCALE 0.125f

#define N1 3840
#define N2 1024
#define V2 2560

// ---------------- scratch ----------------------------------------------------
__device__ float g_C1 [BT * N1];
// fp16 blob for gemm1: A(hi,lo), B(hi) all rows, B(lo) for SsSd rows
#define A1Hf 0
#define A1Lf (BT * 1024)
#define B1Hf (2 * BT * 1024)
#define B1Lf (2 * BT * 1024 + N1 * 1024)
__device__ __half g_W1f[2 * BT * 1024 + 2 * N1 * 1024];
// fp16 blob for gemm2 (plain 1-term)
#define A2H 0
#define B2H (BT * V2)
__device__ __half g_W2[BT * V2 + N2 * V2];

__device__ float g_sdg[BT * HE];
// attention operands: packed fp16x2 pairs
__device__ uint32_t g_Qh[16 * 1024 * 32];   // [bh][t][dpair]
__device__ uint32_t g_Ql[16 * 1024 * 32];
__device__ uint32_t g_Kh[16 * 1024 * 32];   // single-rounded fp16
__device__ uint32_t g_Vh[16 * 64 * 512];    // [bh][d][tpair], single-rounded fp16

// ---------------- helpers -----------------------------------------------------
__device__ __forceinline__ uint32_t smem_u32(const void* p) {
    uint32_t a;
    asm("{ .reg .u64 t; cvta.to.shared.u64 t, %1; cvt.u32.u64 %0, t; }" : "=r"(a) : "l"(p));
    return a;
}
__device__ __forceinline__ void cpasync16(uint32_t dst, const void* src) {
    asm volatile("cp.async.cg.shared.global [%0], [%1], 16;\n" :: "r"(dst), "l"(src));
}
__device__ __forceinline__ void cp_commit() { asm volatile("cp.async.commit_group;\n"); }
template<int N> __device__ __forceinline__ void cp_wait() { asm volatile("cp.async.wait_group %0;\n" :: "n"(N)); }

__device__ __forceinline__ void mma16816f(float* c, const uint32_t* a, const uint32_t* b) {
    asm volatile(
        "mma.sync.aligned.m16n8k16.row.col.f32.f16.f16.f32 "
        "{%0,%1,%2,%3}, {%4,%5,%6,%7}, {%8,%9}, {%0,%1,%2,%3};"
        : "+f"(c[0]), "+f"(c[1]), "+f"(c[2]), "+f"(c[3])
        : "r"(a[0]), "r"(a[1]), "r"(a[2]), "r"(a[3]), "r"(b[0]), "r"(b[1]));
}
__device__ __forceinline__ void ldm_x4(uint32_t* r, uint32_t addr) {
    asm volatile("ldmatrix.sync.aligned.m8n8.x4.shared.b16 {%0,%1,%2,%3}, [%4];"
        : "=r"(r[0]), "=r"(r[1]), "=r"(r[2]), "=r"(r[3]) : "r"(addr));
}
__device__ __forceinline__ uint32_t packh2(float lo, float hi) {
    __half2 h = __floats2half2_rn(lo, hi);
    return *(uint32_t*)&h;
}
__device__ __forceinline__ uint32_t packh2res(uint32_t p, float lo, float hi) {
    __half2 ph = *(__half2*)&p;
    float2 bk = __half22float2(ph);
    return packh2(lo - bk.x, hi - bk.y);
}
#define WGBAR(id) asm volatile("bar.sync %0, 128;" :: "r"((id) + 1) : "memory")

// ---------------- fp16 GEMM, configurable split terms ------------------------
// C = Ah@Bh^T (+ Al@Bh^T if ASPLIT) (+ Ah@Bl^T if BSPLIT)
// FUSEQK: tiles with n0<1024 write fp16 Q(split)/K(rounded) pair arrays.
template<int NT, int KTOT, bool FUSEQK, bool ASPLIT, bool BSPLIT>
__device__ __forceinline__ void gemmf_body(const char* __restrict__ W,
                                           uint32_t offAh, uint32_t offAl,
                                           uint32_t offBh, uint32_t offBl,
                                           float* __restrict__ C, int Ntot)
{
    constexpr int AR    = ASPLIT ? 256 : 128;
    constexpr int AC    = ASPLIT ? 4 : 2;          // A cp.async chunks
    constexpr int ROWS  = AR + (BSPLIT ? 2 : 1) * NT;
    constexpr int STAGE = ROWS * 64;
    constexpr int NSTEP = KTOT / 32;
    constexpr int NTW   = NT / 2;
    constexpr int NPAIR = NTW / 16;
    constexpr int NA    = NTW / 8;
    constexpr int CPT   = ROWS / 64;
    constexpr int NB    = NT / 64;
    constexpr size_t K2B = KTOT * 2;

    extern __shared__ char sm_raw[];
    const uint32_t sb = smem_u32(sm_raw);
    const int tid = threadIdx.x, wid = tid >> 5, lane = tid & 31;
    const int wm = wid & 3, wn = wid >> 2;
    const int m0 = blockIdx.y * 128, n0 = blockIdx.x * NT;

    const int r0 = tid >> 2;
    const int cc = (tid & 3) * 16;
    const uint32_t dst0 = r0 * 64 + (cc ^ (((r0 >> 1) & 3) * 16));
    const char* pAh = W + offAh + (size_t)(m0 + r0) * K2B + cc;
    const char* pAl = W + offAl + (size_t)(m0 + r0) * K2B + cc;
    const char* pBh = W + offBh + (size_t)(n0 + r0) * K2B + cc;
    const char* pBl = W + offBl + (size_t)(n0 + r0) * K2B + cc;

    auto issue = [&](int kt, int slot) {
        const uint32_t st = sb + slot * STAGE + dst0;
        const size_t gk = (size_t)kt * 64;
#pragma unroll
        for (int i = 0; i < CPT; i++) {
            const char* src;
            if      (i < 2)            src = pAh + (size_t)i * (64 * K2B);
            else if (ASPLIT && i < AC) src = pAl + (size_t)(i - 2) * (64 * K2B);
            else if (i < AC + NB)      src = pBh + (size_t)(i - AC) * (64 * K2B);
            else                       src = pBl + (size_t)(i - AC - NB) * (64 * K2B);
            cpasync16(st + i * 4096, src + gk);
        }
    };

    const uint32_t ahi = (lane >> 4) * 16;
    const uint32_t bhi = ((lane >> 3) & 1) * 16;
    uint32_t aof[2], aswz[2], bof[NPAIR], bswz[NPAIR];
#pragma unroll
    for (int mi = 0; mi < 2; mi++) {
        int r = wm * 32 + mi * 16 + (lane & 15);
        aof[mi] = r * 64; aswz[mi] = ((r >> 1) & 3) * 16;
    }
#pragma unroll
    for (int pj = 0; pj < NPAIR; pj++) {
        int r = wn * NTW + pj * 16 + ((lane >> 4) << 3) + (lane & 7);
        bof[pj] = (AR + r) * 64; bswz[pj] = ((r >> 1) & 3) * 16;
    }

    float acc[2][NA][4];
#pragma unroll
    for (int mi = 0; mi < 2; mi++)
#pragma unroll
        for (int na = 0; na < NA; na++)
#pragma unroll
            for (int q = 0; q < 4; q++) acc[mi][na][q] = 0.f;

    issue(0, 0); cp_commit();
    issue(1, 1); cp_commit();

    for (int kt = 0; kt < NSTEP; kt++) {
        if (kt + 1 < NSTEP) cp_wait<1>(); else cp_wait<0>();
        __syncthreads();
        if (kt + 2 < NSTEP) { issue(kt + 2, (kt + 2) % 3); cp_commit(); }

        uint32_t stg = sb + (kt % 3) * STAGE;
#pragma unroll
        for (int ks = 0; ks < 2; ks++) {
            const uint32_t ca = (uint32_t)ks * 32 + ahi;
            const uint32_t cb = (uint32_t)ks * 32 + bhi;
            uint32_t ah[2][4], al[2][4], bb[NPAIR][4];
            ldm_x4(ah[0], stg + aof[0] + (ca ^ aswz[0]));
            ldm_x4(ah[1], stg + aof[1] + (ca ^ aswz[1]));
            if (ASPLIT) {
                ldm_x4(al[0], stg + 8192 + aof[0] + (ca ^ aswz[0]));
                ldm_x4(al[1], stg + 8192 + aof[1] + (ca ^ aswz[1]));
            }
#pragma unroll
            for (int pj = 0; pj < NPAIR; pj++)
                ldm_x4(bb[pj], stg + bof[pj] + (cb ^ bswz[pj]));
#pragma unroll
            for (int mi = 0; mi < 2; mi++)
#pragma unroll
                for (int pj = 0; pj < NPAIR; pj++) {
                    mma16816f(acc[mi][2 * pj],     ah[mi], &bb[pj][0]);
                    mma16816f(acc[mi][2 * pj + 1], ah[mi], &bb[pj][2]);
                }
            if (ASPLIT) {
#pragma unroll
                for (int mi = 0; mi < 2; mi++)
#pragma unroll
                    for (int pj = 0; pj < NPAIR; pj++) {
                        mma16816f(acc[mi][2 * pj],     al[mi], &bb[pj][0]);
                        mma16816f(acc[mi][2 * pj + 1], al[mi], &bb[pj][2]);
                    }
            }
            if (BSPLIT) {
#pragma unroll
                for (int pj = 0; pj < NPAIR; pj++)
                    ldm_x4(bb[pj], stg + bof[pj] + NT * 64 + (cb ^ bswz[pj]));
#pragma unroll
                for (int mi = 0; mi < 2; mi++)
#pragma unroll
                    for (int pj = 0; pj < NPAIR; pj++) {
                        mma16816f(acc[mi][2 * pj],     ah[mi], &bb[pj][0]);
                        mma16816f(acc[mi][2 * pj + 1], ah[mi], &bb[pj][2]);
                    }
            }
        }
    }

    const int g  = lane >> 2;
    const int tg = lane & 3;

    if (FUSEQK && n0 < 1024) {
        const bool isQ = (n0 < 512);
        const float sc = isQ ? QSCALE : 1.0f;
#pragma unroll
        for (int mi = 0; mi < 2; mi++) {
            int r = m0 + wm * 32 + mi * 16 + g;
            int b_ = r >> 10, t = r & 1023;
#pragma unroll
            for (int na = 0; na < NA; na++) {
                int ccc = n0 + wn * NTW + na * 8 + tg * 2;
                int h = (ccc >> 6) & 7;
                int p = (ccc & 63) >> 1;
                size_t base = (((size_t)(b_ * 8 + h) << 10) + t) * 32 + p;
                float v0 = acc[mi][na][0] * sc, v1 = acc[mi][na][1] * sc;
                float w0 = acc[mi][na][2] * sc, w1 = acc[mi][na][3] * sc;
                uint32_t h0 = packh2(v0, v1);
                uint32_t h1 = packh2(w0, w1);
                if (isQ) {
                    g_Qh[base] = h0; g_Ql[base] = packh2res(h0, v0, v1);
                    g_Qh[base + 8 * 32] = h1; g_Ql[base + 8 * 32] = packh2res(h1, w0, w1);
                } else {
                    g_Kh[base] = h0;
                    g_Kh[base + 8 * 32] = h1;
                }
            }
        }
    } else {
#pragma unroll
        for (int mi = 0; mi < 2; mi++) {
            int r = m0 + wm * 32 + mi * 16 + g;
#pragma unroll
            for (int na = 0; na < NA; na++) {
                int ccc = n0 + wn * NTW + na * 8 + tg * 2;
                *(float2*)(C + (size_t)r * Ntot + ccc)       = make_float2(acc[mi][na][0], acc[mi][na][1]);
                *(float2*)(C + (size_t)(r + 8) * Ntot + ccc) = make_float2(acc[mi][na][2], acc[mi][na][3]);
            }
        }
    }
}

#define GEMM1_SMEM (3 * (256 + 128) * 64)   // 73728 (3-term NT=64 worst case)
#define GEMM2_SMEM (3 * (128 + 64) * 64)    // 36864 (1-term NT=64)

__global__ __launch_bounds__(256, 3)
void gemm1() {
    if (blockIdx.x < 16)       // Q (0-7) + K (8-15), fused epilogue, 2-term
        gemmf_body<64, 1024, true,  true, false>((const char*)g_W1f, A1Hf*2, A1Lf*2, B1Hf*2, B1Lf*2, g_C1, N1);
    else if (blockIdx.x < 56)  // V tiles, 2-term
        gemmf_body<64, 1024, false, true, false>((const char*)g_W1f, A1Hf*2, A1Lf*2, B1Hf*2, B1Lf*2, g_C1, N1);
    else                       // SsSd tiles (56,57): fp16 3-term (near-fp32)
        gemmf_body<64, 1024, false, true, true >((const char*)g_W1f, A1Hf*2, A1Lf*2, B1Hf*2, B1Lf*2, g_C1, N1);
}
__global__ __launch_bounds__(256, 3)
void gemm2(float* __restrict__ out) {
    gemmf_body<64, 2560, false, false, false>((const char*)g_W2, A2H*2, 0, B2H*2, 0, out, N2);
}

// ---------------- prep kernels ----------------------------------------------
__global__ __launch_bounds__(256) void prep_a1(const float* __restrict__ x) {
    int gid = blockIdx.x * 256 + threadIdx.x;
    float v = x[gid];
    __half fh = __float2half_rn(v);
    __half fl = __float2half_rn(v - __half2float(fh));
    g_W1f[A1Hf + gid] = fh;
    g_W1f[A1Lf + gid] = fl;
}

__global__ void prep_b1(const float* __restrict__ Wq, const float* __restrict__ Wk,
                        const float* __restrict__ Wv, const float* __restrict__ Ws,
                        const float* __restrict__ Wd)
{
    __shared__ float tile[32][33];
    int k0 = blockIdx.x * 32;
    int n0 = blockIdx.y * 32;
    int tx = threadIdx.x, ty = threadIdx.y;
#pragma unroll
    for (int yy = 0; yy < 32; yy += 8) {
        int k = k0 + ty + yy, n = n0 + tx;
        float w;
        if      (n < 512)  w = Wq[(size_t)k * 512  + n];
        else if (n < 1024) w = Wk[(size_t)k * 512  + n - 512];
        else if (n < 3584) w = Wv[(size_t)k * 2560 + n - 1024];
        else if (n < 3624) w = Ws[(size_t)k * 40   + n - 3584];
        else if (n < 3664) w = Wd[(size_t)k * 40   + n - 3624];
        else               w = 0.f;
        tile[ty + yy][tx] = w;
    }
    __syncthreads();
#pragma unroll
    for (int yy = 0; yy < 32; yy += 8) {
        int n = n0 + ty + yy, k = k0 + tx;
        float w = tile[tx][ty + yy];
        int idx = n * 1024 + k;
        __half fh = __float2half_rn(w);
        g_W1f[B1Hf + idx] = fh;
        if (n >= 3584)
            g_W1f[B1Lf + idx] = __float2half_rn(w - __half2float(fh));
    }
}

__global__ __launch_bounds__(256) void prep_b2(const float* __restrict__ Wo) {
    int gid = blockIdx.x * 256 + threadIdx.x;
    int he = gid >> 16;
    int d  = (gid >> 6) & 1023;
    int c  = gid & 63;
    g_W2[B2H + d * V2 + he * 64 + c] = __float2half_rn(Wo[gid]);
}

// ---------------- fused routing gates + expert V mix + transposed pack -------
__global__ __launch_bounds__(256) void route_pack() {
    __shared__ uint32_t tvh[4][65];
    int gid = blockIdx.x * 256 + threadIdx.x;
    int d  = gid & 63;
    int kp = (gid >> 6) & 511;
    int bh = gid >> 15;
    int b = bh >> 3, h = bh & 7;

    float v[2];
#pragma unroll
    for (int u = 0; u < 2; u++) {
        int t = kp * 2 + u;
        const float* row = g_C1 + (size_t)(b * 1024 + t) * N1;
        const float* sl = row + 3584 + h * Ee;
        float s[Ee];
#pragma unroll
        for (int e = 0; e < Ee; e++) s[e] = sl[e];
        float acc = 0.f;
#pragma unroll
        for (int e = 0; e < Ee; e++) {
            int rank = 0;
#pragma unroll
            for (int j = 0; j < Ee; j++)
                rank += (s[j] > s[e]) || (s[j] == s[e] && j < e);
            float gate = (rank < KK) ? 1.0f / (1.0f + expf(-s[e])) : 0.f;
            acc = fmaf(gate, row[1024 + (h * Ee + e) * 64 + d], acc);
        }
        v[u] = acc;

        if (d < Ee) {
            const float* dl = row + 3624 + h * Ee;
            float tq[Ee];
#pragma unroll
            for (int e = 0; e < Ee; e++) tq[e] = dl[e];
            int e = d, rank = 0;
#pragma unroll
            for (int j = 0; j < Ee; j++)
                rank += (tq[j] > tq[e]) || (tq[j] == tq[e] && j < e);
            g_sdg[(b * 1024 + t) * HE + h * Ee + e] = (rank < KK) ? 1.f : 0.f;
        }
    }
    tvh[kp & 3][d] = packh2(v[0], v[1]);
    __syncthreads();
    int td  = threadIdx.x >> 2;
    int tk4 = threadIdx.x & 3;
    int kp0 = (blockIdx.x * 4) & 511;
    g_Vh[((size_t)bh * 64 + td) * 512 + kp0 + tk4] = tvh[tk4][td];
}

// ---------------- tensor-core causal flash attention (fp16 2-term) -----------
#define AQS   (64 * 36)
#define ATL   (64 * 36)
#define ASTG  (2 * ATL)
#define AWG_U (2 * AQS + 2 * ASTG)
#define ATTN_SMEM (2 * AWG_U * 4)

__global__ __launch_bounds__(256) void attn_tc() {
    extern __shared__ uint32_t sm[];
    const int bh   = blockIdx.y;
    const int b    = bh >> 3, h = bh & 7;
    const int wg   = threadIdx.x >> 7;
    const int qt   = wg ? (15 - blockIdx.x) : blockIdx.x;
    const int tid  = threadIdx.x & 127;
    const int w    = tid >> 5;
    const int lane = tid & 31;
    const int g    = lane >> 2;
    const int tig  = lane & 3;
    uint32_t* smg  = sm + wg * AWG_U;
    const uint32_t sb = smem_u32(smg);

    auto issue = [&](int kt, int s) {
#pragma unroll
        for (int i = 0; i < 8; i++) {
            int a = i >> 2;
            int r = (i & 3) * 16 + (tid >> 3);
            int c = tid & 7;
            uint32_t dst = sb + (2 * AQS + s * ASTG + a * ATL + r * 36) * 4 + c * 16;
            const uint32_t* srcb;
            if (a == 0) srcb = g_Kh + ((size_t)(bh << 10) + kt * 64 + r) * 32;
            else        srcb = g_Vh + ((size_t)bh * 64 + r) * 512 + kt * 32;
            cpasync16(dst, (const char*)srcb + c * 16);
        }
    };
    issue(0, 0); cp_commit();

    {
        const uint32_t* qhsrc = g_Qh + ((size_t)(bh << 10) + qt * 64) * 32;
        const uint32_t* qlsrc = g_Ql + ((size_t)(bh << 10) + qt * 64) * 32;
#pragma unroll
        for (int j = 0; j < 4; j++) {
            int idx = tid + j * 128;
            int row = idx >> 3, po = (idx & 7) * 4;
            *(uint4*)&smg[row * 36 + po]       = *(const uint4*)(qhsrc + row * 32 + po);
            *(uint4*)&smg[AQS + row * 36 + po] = *(const uint4*)(qlsrc + row * 32 + po);
        }
    }
    WGBAR(wg);

    uint32_t qa[2][4][4];
#pragma unroll
    for (int hl = 0; hl < 2; hl++) {
        int qb = hl * AQS;
#pragma unroll
        for (int kb = 0; kb < 4; kb++) {
            qa[hl][kb][0] = smg[qb + (w * 16 + g)     * 36 + kb * 8 + tig];
            qa[hl][kb][1] = smg[qb + (w * 16 + g + 8) * 36 + kb * 8 + tig];
            qa[hl][kb][2] = smg[qb + (w * 16 + g)     * 36 + kb * 8 + 4 + tig];
            qa[hl][kb][3] = smg[qb + (w * 16 + g + 8) * 36 + kb * 8 + 4 + tig];
        }
    }

    const int li   = lane >> 3;
    const uint32_t lbase = (((li >> 1) * 8 + (lane & 7)) * 36 + (li & 1) * 4) * 4;

    float o[8][4];
#pragma unroll
    for (int a = 0; a < 8; a++)
#pragma unroll
        for (int q = 0; q < 4; q++) o[a][q] = 0.f;
    float m[2] = {-1e30f, -1e30f}, l[2] = {0.f, 0.f};

    for (int kt = 0; kt <= qt; kt++) {
        if (kt < qt) { issue(kt + 1, (kt + 1) & 1); cp_commit(); cp_wait<1>(); }
        else         { cp_wait<0>(); }
        WGBAR(wg);

        const uint32_t su  = sb + (2 * AQS + (kt & 1) * ASTG) * 4;
        const uint32_t Khb = su, Vhb = su + ATL * 4;

        float s[8][4];
#pragma unroll
        for (int a = 0; a < 8; a++)
#pragma unroll
            for (int q = 0; q < 4; q++) s[a][q] = 0.f;

#pragma unroll
        for (int kb = 0; kb < 4; kb++) {
            uint32_t bb[4][4];
#pragma unroll
            for (int j = 0; j < 4; j++)
                ldm_x4(bb[j], Khb + lbase + (j * 576 + kb * 8) * 4);
#pragma unroll
            for (int j = 0; j < 4; j++) {
                mma16816f(s[2*j],   qa[0][kb], &bb[j][0]);
                mma16816f(s[2*j+1], qa[0][kb], &bb[j][2]);
            }
#pragma unroll
            for (int j = 0; j < 4; j++) {
                mma16816f(s[2*j],   qa[1][kb], &bb[j][0]);
                mma16816f(s[2*j+1], qa[1][kb], &bb[j][2]);
            }
        }

        if (kt == qt) {
            int r0 = w * 16 + g;
#pragma unroll
            for (int na = 0; na < 8; na++) {
                int c0 = na * 8 + 2 * tig;
                if (c0     > r0)     s[na][0] = -1e9f;
                if (c0 + 1 > r0)     s[na][1] = -1e9f;
                if (c0     > r0 + 8) s[na][2] = -1e9f;
                if (c0 + 1 > r0 + 8) s[na][3] = -1e9f;
            }
        }

#pragma unroll
        for (int ri = 0; ri < 2; ri++) {
            float mx = -1e30f;
#pragma unroll
            for (int a = 0; a < 8; a++)
                mx = fmaxf(mx, fmaxf(s[a][2 * ri], s[a][2 * ri + 1]));
            mx = fmaxf(mx, __shfl_xor_sync(0xffffffffu, mx, 1));
            mx = fmaxf(mx, __shfl_xor_sync(0xffffffffu, mx, 2));
            float mnew = fmaxf(m[ri], mx);
            float corr = __expf(m[ri] - mnew);
            float rs = 0.f;
#pragma unroll
            for (int a = 0; a < 8; a++) {
                float p0 = __expf(s[a][2 * ri]     - mnew);
                float p1 = __expf(s[a][2 * ri + 1] - mnew);
                s[a][2 * ri] = p0; s[a][2 * ri + 1] = p1;
                rs += p0 + p1;
            }
            rs += __shfl_xor_sync(0xffffffffu, rs, 1);
            rs += __shfl_xor_sync(0xffffffffu, rs, 2);
            l[ri] = l[ri] * corr + rs;
            m[ri] = mnew;
#pragma unroll
            for (int a = 0; a < 8; a++) { o[a][2 * ri] *= corr; o[a][2 * ri + 1] *= corr; }
        }

#pragma unroll
        for (int kb = 0; kb < 4; kb++) {
            uint32_t ph[4], pl[4];
            ph[0] = packh2(s[2*kb][0],   s[2*kb][1]);
            ph[1] = packh2(s[2*kb][2],   s[2*kb][3]);
            ph[2] = packh2(s[2*kb+1][0], s[2*kb+1][1]);
            ph[3] = packh2(s[2*kb+1][2], s[2*kb+1][3]);
            pl[0] = packh2res(ph[0], s[2*kb][0],   s[2*kb][1]);
            pl[1] = packh2res(ph[1], s[2*kb][2],   s[2*kb][3]);
            pl[2] = packh2res(ph[2], s[2*kb+1][0], s[2*kb+1][1]);
            pl[3] = packh2res(ph[3], s[2*kb+1][2], s[2*kb+1][3]);

            uint32_t bb[4][4];
#pragma unroll
            for (int j = 0; j < 4; j++)
                ldm_x4(bb[j], Vhb + lbase + (j * 576 + kb * 8) * 4);
#pragma unroll
            for (int j = 0; j < 4; j++) {
                mma16816f(o[2*j],   ph, &bb[j][0]);
                mma16816f(o[2*j+1], ph, &bb[j][2]);
            }
#pragma unroll
            for (int j = 0; j < 4; j++) {
                mma16816f(o[2*j],   pl, &bb[j][0]);
                mma16816f(o[2*j+1], pl, &bb[j][2]);
            }
        }
        WGBAR(wg);
    }

    // ---- fused epilogue: A2 = fp16(sd * O) for all 5 experts (hi only) ----
    float inv0 = 1.0f / l[0], inv1 = 1.0f / l[1];
    int row0 = qt * 64 + w * 16 + g;
    int bt0  = b * 1024 + row0;

    float g0[Ee], g1[Ee];
#pragma unroll
    for (int e = 0; e < Ee; e++) {
        g0[e] = g_sdg[bt0 * HE + h * Ee + e];
        g1[e] = g_sdg[(bt0 + 8) * HE + h * Ee + e];
    }
    uint32_t* a2h0 = (uint32_t*)(g_W2 + A2H + (size_t)bt0 * V2);
    uint32_t* a2h1 = (uint32_t*)(g_W2 + A2H + (size_t)(bt0 + 8) * V2);

#pragma unroll
    for (int na = 0; na < 8; na++) {
        int c0 = na * 8 + 2 * tig;
        float v00 = o[na][0] * inv0, v01 = o[na][1] * inv0;
        float v10 = o[na][2] * inv1, v11 = o[na][3] * inv1;
        uint32_t h0u = packh2(v00, v01);
        uint32_t h1u = packh2(v10, v11);
#pragma unroll
        for (int e = 0; e < Ee; e++) {
            int cw = ((h * Ee + e) * 64 + c0) >> 1;
            a2h0[cw] = (g0[e] != 0.f) ? h0u : 0u;
            a2h1[cw] = (g1[e] != 0.f) ? h1u : 0u;
        }
    }
}

// ---------------- launch ------------------------------------------------------
extern "C" void kernel_launch(void* const* d_in, const int* in_sizes, int n_in,
                              void* d_out, int out_size)
{
    const float* x  = (const float*)d_in[0];
    const float* Wq = (const float*)d_in[1];
    const float* Wk = (const float*)d_in[2];
    const float* Wv = (const float*)d_in[3];
    const float* Ws = (const float*)d_in[4];
    const float* Wd = (const float*)d_in[5];
    const float* Wo = (const float*)d_in[6];
    float* out = (float*)d_out;

    cudaFuncSetAttribute(gemm1,   cudaFuncAttributeMaxDynamicSharedMemorySize, GEMM1_SMEM);
    cudaFuncSetAttribute(gemm2,   cudaFuncAttributeMaxDynamicSharedMemorySize, GEMM2_SMEM);
    cudaFuncSetAttribute(attn_tc, cudaFuncAttributeMaxDynamicSharedMemorySize, ATTN_SMEM);

    prep_a1   <<<BT * DIMD / 256, 256>>>(x);
    prep_b1   <<<dim3(32, 120), dim3(32, 8)>>>(Wq, Wk, Wv, Ws, Wd);
    prep_b2   <<<HE * DIMD * 64 / 256, 256>>>(Wo);
    gemm1     <<<dim3(58, 16), 256, GEMM1_SMEM>>>();
    route_pack<<<16 * 512 * 64 / 256, 256>>>();
    attn_tc   <<<dim3(8, 16), 256, ATTN_SMEM>>>();
    gemm2     <<<dim3(N2 / 64, BT / 128), 256, GEMM2_SMEM>>>(out);
}

// round 14
// speedup vs baseline: 1.4027x; 1.1338x over previous
#include <cuda_runtime.h>
#include <cuda_fp16.h>
#include <cstdint>

#define Tt   1024
#define DIMD 1024
#define Hh   8
#define Ee   5
#define KK   3
#define BT   2048
#define HS   512
#define HE   40
#define QSCALE 0.125f

#define N1 3840
#define N2 1024
#define V2 2560

// ---------------- scratch ----------------------------------------------------
__device__ float g_C1 [BT * N1];
// fp16 blob for gemm1: A(hi,lo), B(hi) all rows, B(lo) for SsSd rows
#define A1Hf 0
#define A1Lf (BT * 1024)
#define B1Hf (2 * BT * 1024)
#define B1Lf (2 * BT * 1024 + N1 * 1024)
__device__ __half g_W1f[2 * BT * 1024 + 2 * N1 * 1024];
// fp16 blob for gemm2 (plain 1-term)
#define A2H 0
#define B2H (BT * V2)
__device__ __half g_W2[BT * V2 + N2 * V2];

__device__ float g_sdg[BT * HE];
// attention operands: packed fp16x2 pairs
__device__ uint32_t g_Qh[16 * 1024 * 32];   // [bh][t][dpair]
__device__ uint32_t g_Ql[16 * 1024 * 32];
__device__ uint32_t g_Kh[16 * 1024 * 32];   // single-rounded fp16
__device__ uint32_t g_Vh[16 * 64 * 512];    // [bh][d][tpair], single-rounded fp16

// ---------------- helpers -----------------------------------------------------
__device__ __forceinline__ uint32_t smem_u32(const void* p) {
    uint32_t a;
    asm("{ .reg .u64 t; cvta.to.shared.u64 t, %1; cvt.u32.u64 %0, t; }" : "=r"(a) : "l"(p));
    return a;
}
__device__ __forceinline__ void cpasync16(uint32_t dst, const void* src) {
    asm volatile("cp.async.cg.shared.global [%0], [%1], 16;\n" :: "r"(dst), "l"(src));
}
__device__ __forceinline__ void cp_commit() { asm volatile("cp.async.commit_group;\n"); }
template<int N> __device__ __forceinline__ void cp_wait() { asm volatile("cp.async.wait_group %0;\n" :: "n"(N)); }

__device__ __forceinline__ void mma16816f(float* c, const uint32_t* a, const uint32_t* b) {
    asm volatile(
        "mma.sync.aligned.m16n8k16.row.col.f32.f16.f16.f32 "
        "{%0,%1,%2,%3}, {%4,%5,%6,%7}, {%8,%9}, {%0,%1,%2,%3};"
        : "+f"(c[0]), "+f"(c[1]), "+f"(c[2]), "+f"(c[3])
        : "r"(a[0]), "r"(a[1]), "r"(a[2]), "r"(a[3]), "r"(b[0]), "r"(b[1]));
}
__device__ __forceinline__ void ldm_x4(uint32_t* r, uint32_t addr) {
    asm volatile("ldmatrix.sync.aligned.m8n8.x4.shared.b16 {%0,%1,%2,%3}, [%4];"
        : "=r"(r[0]), "=r"(r[1]), "=r"(r[2]), "=r"(r[3]) : "r"(addr));
}
__device__ __forceinline__ uint32_t packh2(float lo, float hi) {
    __half2 h = __floats2half2_rn(lo, hi);
    return *(uint32_t*)&h;
}
__device__ __forceinline__ uint32_t packh2res(uint32_t p, float lo, float hi) {
    __half2 ph = *(__half2*)&p;
    float2 bk = __half22float2(ph);
    return packh2(lo - bk.x, hi - bk.y);
}
#define WGBAR(id) asm volatile("bar.sync %0, 128;" :: "r"((id) + 1) : "memory")

// ---------------- fp16 GEMM, configurable split terms ------------------------
// C = Ah@Bh^T (+ Al@Bh^T if ASPLIT) (+ Ah@Bl^T if BSPLIT)
// FUSEQK: tiles with n0<1024 write fp16 Q(split)/K(rounded) pair arrays.
template<int NT, int KTOT, bool FUSEQK, bool ASPLIT, bool BSPLIT>
__device__ __forceinline__ void gemmf_body(const char* __restrict__ W,
                                           uint32_t offAh, uint32_t offAl,
                                           uint32_t offBh, uint32_t offBl,
                                           float* __restrict__ C, int Ntot)
{
    constexpr int AR    = ASPLIT ? 256 : 128;
    constexpr int AC    = ASPLIT ? 4 : 2;
    constexpr int ROWS  = AR + (BSPLIT ? 2 : 1) * NT;
    constexpr int STAGE = ROWS * 64;
    constexpr int NSTEP = KTOT / 32;
    constexpr int NTW   = NT / 2;
    constexpr int NPAIR = NTW / 16;
    constexpr int NA    = NTW / 8;
    constexpr int CPT   = ROWS / 64;
    constexpr int NB    = NT / 64;
    constexpr size_t K2B = KTOT * 2;

    extern __shared__ char sm_raw[];
    const uint32_t sb = smem_u32(sm_raw);
    const int tid = threadIdx.x, wid = tid >> 5, lane = tid & 31;
    const int wm = wid & 3, wn = wid >> 2;
    const int m0 = blockIdx.y * 128, n0 = blockIdx.x * NT;

    const int r0 = tid >> 2;
    const int cc = (tid & 3) * 16;
    const uint32_t dst0 = r0 * 64 + (cc ^ (((r0 >> 1) & 3) * 16));
    const char* pAh = W + offAh + (size_t)(m0 + r0) * K2B + cc;
    const char* pAl = W + offAl + (size_t)(m0 + r0) * K2B + cc;
    const char* pBh = W + offBh + (size_t)(n0 + r0) * K2B + cc;
    const char* pBl = W + offBl + (size_t)(n0 + r0) * K2B + cc;

    auto issue = [&](int kt, int slot) {
        const uint32_t st = sb + slot * STAGE + dst0;
        const size_t gk = (size_t)kt * 64;
#pragma unroll
        for (int i = 0; i < CPT; i++) {
            const char* src;
            if      (i < 2)            src = pAh + (size_t)i * (64 * K2B);
            else if (ASPLIT && i < AC) src = pAl + (size_t)(i - 2) * (64 * K2B);
            else if (i < AC + NB)      src = pBh + (size_t)(i - AC) * (64 * K2B);
            else                       src = pBl + (size_t)(i - AC - NB) * (64 * K2B);
            cpasync16(st + i * 4096, src + gk);
        }
    };

    const uint32_t ahi = (lane >> 4) * 16;
    const uint32_t bhi = ((lane >> 3) & 1) * 16;
    uint32_t aof[2], aswz[2], bof[NPAIR], bswz[NPAIR];
#pragma unroll
    for (int mi = 0; mi < 2; mi++) {
        int r = wm * 32 + mi * 16 + (lane & 15);
        aof[mi] = r * 64; aswz[mi] = ((r >> 1) & 3) * 16;
    }
#pragma unroll
    for (int pj = 0; pj < NPAIR; pj++) {
        int r = wn * NTW + pj * 16 + ((lane >> 4) << 3) + (lane & 7);
        bof[pj] = (AR + r) * 64; bswz[pj] = ((r >> 1) & 3) * 16;
    }

    float acc[2][NA][4];
#pragma unroll
    for (int mi = 0; mi < 2; mi++)
#pragma unroll
        for (int na = 0; na < NA; na++)
#pragma unroll
            for (int q = 0; q < 4; q++) acc[mi][na][q] = 0.f;

    issue(0, 0); cp_commit();
    issue(1, 1); cp_commit();

    for (int kt = 0; kt < NSTEP; kt++) {
        if (kt + 1 < NSTEP) cp_wait<1>(); else cp_wait<0>();
        __syncthreads();
        if (kt + 2 < NSTEP) { issue(kt + 2, (kt + 2) % 3); cp_commit(); }

        uint32_t stg = sb + (kt % 3) * STAGE;
#pragma unroll
        for (int ks = 0; ks < 2; ks++) {
            const uint32_t ca = (uint32_t)ks * 32 + ahi;
            const uint32_t cb = (uint32_t)ks * 32 + bhi;
            uint32_t ah[2][4], al[2][4], bb[NPAIR][4];
            ldm_x4(ah[0], stg + aof[0] + (ca ^ aswz[0]));
            ldm_x4(ah[1], stg + aof[1] + (ca ^ aswz[1]));
            if (ASPLIT) {
                ldm_x4(al[0], stg + 8192 + aof[0] + (ca ^ aswz[0]));
                ldm_x4(al[1], stg + 8192 + aof[1] + (ca ^ aswz[1]));
            }
#pragma unroll
            for (int pj = 0; pj < NPAIR; pj++)
                ldm_x4(bb[pj], stg + bof[pj] + (cb ^ bswz[pj]));
#pragma unroll
            for (int mi = 0; mi < 2; mi++)
#pragma unroll
                for (int pj = 0; pj < NPAIR; pj++) {
                    mma16816f(acc[mi][2 * pj],     ah[mi], &bb[pj][0]);
                    mma16816f(acc[mi][2 * pj + 1], ah[mi], &bb[pj][2]);
                }
            if (ASPLIT) {
#pragma unroll
                for (int mi = 0; mi < 2; mi++)
#pragma unroll
                    for (int pj = 0; pj < NPAIR; pj++) {
                        mma16816f(acc[mi][2 * pj],     al[mi], &bb[pj][0]);
                        mma16816f(acc[mi][2 * pj + 1], al[mi], &bb[pj][2]);
                    }
            }
            if (BSPLIT) {
#pragma unroll
                for (int pj = 0; pj < NPAIR; pj++)
                    ldm_x4(bb[pj], stg + bof[pj] + NT * 64 + (cb ^ bswz[pj]));
#pragma unroll
                for (int mi = 0; mi < 2; mi++)
#pragma unroll
                    for (int pj = 0; pj < NPAIR; pj++) {
                        mma16816f(acc[mi][2 * pj],     ah[mi], &bb[pj][0]);
                        mma16816f(acc[mi][2 * pj + 1], ah[mi], &bb[pj][2]);
                    }
            }
        }
    }

    const int g  = lane >> 2;
    const int tg = lane & 3;

    if (FUSEQK && n0 < 1024) {
        const bool isQ = (n0 < 512);
        const float sc = isQ ? QSCALE : 1.0f;
#pragma unroll
        for (int mi = 0; mi < 2; mi++) {
            int r = m0 + wm * 32 + mi * 16 + g;
            int b_ = r >> 10, t = r & 1023;
#pragma unroll
            for (int na = 0; na < NA; na++) {
                int ccc = n0 + wn * NTW + na * 8 + tg * 2;
                int h = (ccc >> 6) & 7;
                int p = (ccc & 63) >> 1;
                size_t base = (((size_t)(b_ * 8 + h) << 10) + t) * 32 + p;
                float v0 = acc[mi][na][0] * sc, v1 = acc[mi][na][1] * sc;
                float w0 = acc[mi][na][2] * sc, w1 = acc[mi][na][3] * sc;
                uint32_t h0 = packh2(v0, v1);
                uint32_t h1 = packh2(w0, w1);
                if (isQ) {
                    g_Qh[base] = h0; g_Ql[base] = packh2res(h0, v0, v1);
                    g_Qh[base + 8 * 32] = h1; g_Ql[base + 8 * 32] = packh2res(h1, w0, w1);
                } else {
                    g_Kh[base] = h0;
                    g_Kh[base + 8 * 32] = h1;
                }
            }
        }
    } else {
#pragma unroll
        for (int mi = 0; mi < 2; mi++) {
            int r = m0 + wm * 32 + mi * 16 + g;
#pragma unroll
            for (int na = 0; na < NA; na++) {
                int ccc = n0 + wn * NTW + na * 8 + tg * 2;
                *(float2*)(C + (size_t)r * Ntot + ccc)       = make_float2(acc[mi][na][0], acc[mi][na][1]);
                *(float2*)(C + (size_t)(r + 8) * Ntot + ccc) = make_float2(acc[mi][na][2], acc[mi][na][3]);
            }
        }
    }
}

#define GEMM1_SMEM (3 * (256 + 128) * 64)   // 73728 (3-term NT=64 worst case)
#define GEMM2_SMEM (3 * (128 + 64) * 64)    // 36864 (1-term NT=64)

__global__ __launch_bounds__(256, 3)
void gemm1() {
    if (blockIdx.x < 16)       // Q (0-7) + K (8-15), fused epilogue, 2-term
        gemmf_body<64, 1024, true,  true,  false>((const char*)g_W1f, A1Hf*2, A1Lf*2, B1Hf*2, B1Lf*2, g_C1, N1);
    else if (blockIdx.x < 56)  // V tiles: plain fp16 1-term (linear path)
        gemmf_body<64, 1024, false, false, false>((const char*)g_W1f, A1Hf*2, A1Lf*2, B1Hf*2, B1Lf*2, g_C1, N1);
    else                       // SsSd tiles (56,57): fp16 3-term (near-fp32)
        gemmf_body<64, 1024, false, true,  true >((const char*)g_W1f, A1Hf*2, A1Lf*2, B1Hf*2, B1Lf*2, g_C1, N1);
}
__global__ __launch_bounds__(256, 3)
void gemm2(float* __restrict__ out) {
    gemmf_body<64, 2560, false, false, false>((const char*)g_W2, A2H*2, 0, B2H*2, 0, out, N2);
}

// ---------------- prep kernels ----------------------------------------------
// merged: x split (blocks 0..8191) + Wo pack (blocks 8192..18431)
__global__ __launch_bounds__(256) void prep_misc(const float* __restrict__ x,
                                                 const float* __restrict__ Wo) {
    int bid = blockIdx.x;
    if (bid < 8192) {
        int gid = bid * 256 + threadIdx.x;
        float v = x[gid];
        __half fh = __float2half_rn(v);
        __half fl = __float2half_rn(v - __half2float(fh));
        g_W1f[A1Hf + gid] = fh;
        g_W1f[A1Lf + gid] = fl;
    } else {
        int gid = (bid - 8192) * 256 + threadIdx.x;
        int he = gid >> 16;
        int d  = (gid >> 6) & 1023;
        int c  = gid & 63;
        g_W2[B2H + d * V2 + he * 64 + c] = __float2half_rn(Wo[gid]);
    }
}

__global__ void prep_b1(const float* __restrict__ Wq, const float* __restrict__ Wk,
                        const float* __restrict__ Wv, const float* __restrict__ Ws,
                        const float* __restrict__ Wd)
{
    __shared__ float tile[32][33];
    int k0 = blockIdx.x * 32;
    int n0 = blockIdx.y * 32;
    int tx = threadIdx.x, ty = threadIdx.y;
#pragma unroll
    for (int yy = 0; yy < 32; yy += 8) {
        int k = k0 + ty + yy, n = n0 + tx;
        float w;
        if      (n < 512)  w = Wq[(size_t)k * 512  + n];
        else if (n < 1024) w = Wk[(size_t)k * 512  + n - 512];
        else if (n < 3584) w = Wv[(size_t)k * 2560 + n - 1024];
        else if (n < 3624) w = Ws[(size_t)k * 40   + n - 3584];
        else if (n < 3664) w = Wd[(size_t)k * 40   + n - 3624];
        else               w = 0.f;
        tile[ty + yy][tx] = w;
    }
    __syncthreads();
#pragma unroll
    for (int yy = 0; yy < 32; yy += 8) {
        int n = n0 + ty + yy, k = k0 + tx;
        float w = tile[tx][ty + yy];
        int idx = n * 1024 + k;
        __half fh = __float2half_rn(w);
        g_W1f[B1Hf + idx] = fh;
        if (n >= 3584)
            g_W1f[B1Lf + idx] = __float2half_rn(w - __half2float(fh));
    }
}

// ---------------- fused routing gates + expert V mix + transposed pack -------
__global__ __launch_bounds__(256) void route_pack() {
    __shared__ uint32_t tvh[4][65];
    int gid = blockIdx.x * 256 + threadIdx.x;
    int d  = gid & 63;
    int kp = (gid >> 6) & 511;
    int bh = gid >> 15;
    int b = bh >> 3, h = bh & 7;

    float v[2];
#pragma unroll
    for (int u = 0; u < 2; u++) {
        int t = kp * 2 + u;
        const float* row = g_C1 + (size_t)(b * 1024 + t) * N1;
        const float* sl = row + 3584 + h * Ee;
        float s[Ee];
#pragma unroll
        for (int e = 0; e < Ee; e++) s[e] = sl[e];
        float acc = 0.f;
#pragma unroll
        for (int e = 0; e < Ee; e++) {
            int rank = 0;
#pragma unroll
            for (int j = 0; j < Ee; j++)
                rank += (s[j] > s[e]) || (s[j] == s[e] && j < e);
            float gate = (rank < KK) ? 1.0f / (1.0f + expf(-s[e])) : 0.f;
            acc = fmaf(gate, row[1024 + (h * Ee + e) * 64 + d], acc);
        }
        v[u] = acc;

        if (d < Ee) {
            const float* dl = row + 3624 + h * Ee;
            float tq[Ee];
#pragma unroll
            for (int e = 0; e < Ee; e++) tq[e] = dl[e];
            int e = d, rank = 0;
#pragma unroll
            for (int j = 0; j < Ee; j++)
                rank += (tq[j] > tq[e]) || (tq[j] == tq[e] && j < e);
            g_sdg[(b * 1024 + t) * HE + h * Ee + e] = (rank < KK) ? 1.f : 0.f;
        }
    }
    tvh[kp & 3][d] = packh2(v[0], v[1]);
    __syncthreads();
    int td  = threadIdx.x >> 2;
    int tk4 = threadIdx.x & 3;
    int kp0 = (blockIdx.x * 4) & 511;
    g_Vh[((size_t)bh * 64 + td) * 512 + kp0 + tk4] = tvh[tk4][td];
}

// ---------------- tensor-core causal flash attention (fp16 2-term) -----------
#define AQS   (64 * 36)
#define ATL   (64 * 36)
#define ASTG  (2 * ATL)
#define AWG_U (2 * AQS + 2 * ASTG)
#define ATTN_SMEM (2 * AWG_U * 4)

__global__ __launch_bounds__(256) void attn_tc() {
    extern __shared__ uint32_t sm[];
    const int bh   = blockIdx.y;
    const int b    = bh >> 3, h = bh & 7;
    const int wg   = threadIdx.x >> 7;
    const int qt   = wg ? (15 - blockIdx.x) : blockIdx.x;
    const int tid  = threadIdx.x & 127;
    const int w    = tid >> 5;
    const int lane = tid & 31;
    const int g    = lane >> 2;
    const int tig  = lane & 3;
    uint32_t* smg  = sm + wg * AWG_U;
    const uint32_t sb = smem_u32(smg);

    auto issue = [&](int kt, int s) {
#pragma unroll
        for (int i = 0; i < 8; i++) {
            int a = i >> 2;
            int r = (i & 3) * 16 + (tid >> 3);
            int c = tid & 7;
            uint32_t dst = sb + (2 * AQS + s * ASTG + a * ATL + r * 36) * 4 + c * 16;
            const uint32_t* srcb;
            if (a == 0) srcb = g_Kh + ((size_t)(bh << 10) + kt * 64 + r) * 32;
            else        srcb = g_Vh + ((size_t)bh * 64 + r) * 512 + kt * 32;
            cpasync16(dst, (const char*)srcb + c * 16);
        }
    };
    issue(0, 0); cp_commit();

    {
        const uint32_t* qhsrc = g_Qh + ((size_t)(bh << 10) + qt * 64) * 32;
        const uint32_t* qlsrc = g_Ql + ((size_t)(bh << 10) + qt * 64) * 32;
#pragma unroll
        for (int j = 0; j < 4; j++) {
            int idx = tid + j * 128;
            int row = idx >> 3, po = (idx & 7) * 4;
            *(uint4*)&smg[row * 36 + po]       = *(const uint4*)(qhsrc + row * 32 + po);
            *(uint4*)&smg[AQS + row * 36 + po] = *(const uint4*)(qlsrc + row * 32 + po);
        }
    }
    WGBAR(wg);

    uint32_t qa[2][4][4];
#pragma unroll
    for (int hl = 0; hl < 2; hl++) {
        int qb = hl * AQS;
#pragma unroll
        for (int kb = 0; kb < 4; kb++) {
            qa[hl][kb][0] = smg[qb + (w * 16 + g)     * 36 + kb * 8 + tig];
            qa[hl][kb][1] = smg[qb + (w * 16 + g + 8) * 36 + kb * 8 + tig];
            qa[hl][kb][2] = smg[qb + (w * 16 + g)     * 36 + kb * 8 + 4 + tig];
            qa[hl][kb][3] = smg[qb + (w * 16 + g + 8) * 36 + kb * 8 + 4 + tig];
        }
    }

    const int li   = lane >> 3;
    const uint32_t lbase = (((li >> 1) * 8 + (lane & 7)) * 36 + (li & 1) * 4) * 4;

    float o[8][4];
#pragma unroll
    for (int a = 0; a < 8; a++)
#pragma unroll
        for (int q = 0; q < 4; q++) o[a][q] = 0.f;
    float m[2] = {-1e30f, -1e30f}, l[2] = {0.f, 0.f};

    for (int kt = 0; kt <= qt; kt++) {
        if (kt < qt) { issue(kt + 1, (kt + 1) & 1); cp_commit(); cp_wait<1>(); }
        else         { cp_wait<0>(); }
        WGBAR(wg);

        const uint32_t su  = sb + (2 * AQS + (kt & 1) * ASTG) * 4;
        const uint32_t Khb = su, Vhb = su + ATL * 4;

        float s[8][4];
#pragma unroll
        for (int a = 0; a < 8; a++)
#pragma unroll
            for (int q = 0; q < 4; q++) s[a][q] = 0.f;

#pragma unroll
        for (int kb = 0; kb < 4; kb++) {
            uint32_t bb[4][4];
#pragma unroll
            for (int j = 0; j < 4; j++)
                ldm_x4(bb[j], Khb + lbase + (j * 576 + kb * 8) * 4);
#pragma unroll
            for (int j = 0; j < 4; j++) {
                mma16816f(s[2*j],   qa[0][kb], &bb[j][0]);
                mma16816f(s[2*j+1], qa[0][kb], &bb[j][2]);
            }
#pragma unroll
            for (int j = 0; j < 4; j++) {
                mma16816f(s[2*j],   qa[1][kb], &bb[j][0]);
                mma16816f(s[2*j+1], qa[1][kb], &bb[j][2]);
            }
        }

        if (kt == qt) {
            int r0 = w * 16 + g;
#pragma unroll
            for (int na = 0; na < 8; na++) {
                int c0 = na * 8 + 2 * tig;
                if (c0     > r0)     s[na][0] = -1e9f;
                if (c0 + 1 > r0)     s[na][1] = -1e9f;
                if (c0     > r0 + 8) s[na][2] = -1e9f;
                if (c0 + 1 > r0 + 8) s[na][3] = -1e9f;
            }
        }

#pragma unroll
        for (int ri = 0; ri < 2; ri++) {
            float mx = -1e30f;
#pragma unroll
            for (int a = 0; a < 8; a++)
                mx = fmaxf(mx, fmaxf(s[a][2 * ri], s[a][2 * ri + 1]));
            mx = fmaxf(mx, __shfl_xor_sync(0xffffffffu, mx, 1));
            mx = fmaxf(mx, __shfl_xor_sync(0xffffffffu, mx, 2));
            float mnew = fmaxf(m[ri], mx);
            float corr = __expf(m[ri] - mnew);
            float rs = 0.f;
#pragma unroll
            for (int a = 0; a < 8; a++) {
                float p0 = __expf(s[a][2 * ri]     - mnew);
                float p1 = __expf(s[a][2 * ri + 1] - mnew);
                s[a][2 * ri] = p0; s[a][2 * ri + 1] = p1;
                rs += p0 + p1;
            }
            rs += __shfl_xor_sync(0xffffffffu, rs, 1);
            rs += __shfl_xor_sync(0xffffffffu, rs, 2);
            l[ri] = l[ri] * corr + rs;
            m[ri] = mnew;
#pragma unroll
            for (int a = 0; a < 8; a++) { o[a][2 * ri] *= corr; o[a][2 * ri + 1] *= corr; }
        }

#pragma unroll
        for (int kb = 0; kb < 4; kb++) {
            uint32_t ph[4], pl[4];
            ph[0] = packh2(s[2*kb][0],   s[2*kb][1]);
            ph[1] = packh2(s[2*kb][2],   s[2*kb][3]);
            ph[2] = packh2(s[2*kb+1][0], s[2*kb+1][1]);
            ph[3] = packh2(s[2*kb+1][2], s[2*kb+1][3]);
            pl[0] = packh2res(ph[0], s[2*kb][0],   s[2*kb][1]);
            pl[1] = packh2res(ph[1], s[2*kb][2],   s[2*kb][3]);
            pl[2] = packh2res(ph[2], s[2*kb+1][0], s[2*kb+1][1]);
            pl[3] = packh2res(ph[3], s[2*kb+1][2], s[2*kb+1][3]);

            uint32_t bb[4][4];
#pragma unroll
            for (int j = 0; j < 4; j++)
                ldm_x4(bb[j], Vhb + lbase + (j * 576 + kb * 8) * 4);
#pragma unroll
            for (int j = 0; j < 4; j++) {
                mma16816f(o[2*j],   ph, &bb[j][0]);
                mma16816f(o[2*j+1], ph, &bb[j][2]);
            }
#pragma unroll
            for (int j = 0; j < 4; j++) {
                mma16816f(o[2*j],   pl, &bb[j][0]);
                mma16816f(o[2*j+1], pl, &bb[j][2]);
            }
        }
        WGBAR(wg);
    }

    // ---- fused epilogue: A2 = fp16(sd * O) for all 5 experts ----
    float inv0 = 1.0f / l[0], inv1 = 1.0f / l[1];
    int row0 = qt * 64 + w * 16 + g;
    int bt0  = b * 1024 + row0;

    float g0[Ee], g1[Ee];
#pragma unroll
    for (int e = 0; e < Ee; e++) {
        g0[e] = g_sdg[bt0 * HE + h * Ee + e];
        g1[e] = g_sdg[(bt0 + 8) * HE + h * Ee + e];
    }
    uint32_t* a2h0 = (uint32_t*)(g_W2 + A2H + (size_t)bt0 * V2);
    uint32_t* a2h1 = (uint32_t*)(g_W2 + A2H + (size_t)(bt0 + 8) * V2);

#pragma unroll
    for (int na = 0; na < 8; na++) {
        int c0 = na * 8 + 2 * tig;
        float v00 = o[na][0] * inv0, v01 = o[na][1] * inv0;
        float v10 = o[na][2] * inv1, v11 = o[na][3] * inv1;
        uint32_t h0u = packh2(v00, v01);
        uint32_t h1u = packh2(v10, v11);
#pragma unroll
        for (int e = 0; e < Ee; e++) {
            int cw = ((h * Ee + e) * 64 + c0) >> 1;
            a2h0[cw] = (g0[e] != 0.f) ? h0u : 0u;
            a2h1[cw] = (g1[e] != 0.f) ? h1u : 0u;
        }
    }
}

// ---------------- launch ------------------------------------------------------
extern "C" void kernel_launch(void* const* d_in, const int* in_sizes, int n_in,
                              void* d_out, int out_size)
{
    const float* x  = (const float*)d_in[0];
    const float* Wq = (const float*)d_in[1];
    const float* Wk = (const float*)d_in[2];
    const float* Wv = (const float*)d_in[3];
    const float* Ws = (const float*)d_in[4];
    const float* Wd = (const float*)d_in[5];
    const float* Wo = (const float*)d_in[6];
    float* out = (float*)d_out;

    cudaFuncSetAttribute(gemm1,   cudaFuncAttributeMaxDynamicSharedMemorySize, GEMM1_SMEM);
    cudaFuncSetAttribute(gemm2,   cudaFuncAttributeMaxDynamicSharedMemorySize, GEMM2_SMEM);
    cudaFuncSetAttribute(attn_tc, cudaFuncAttributeMaxDynamicSharedMemorySize, ATTN_SMEM);

    prep_misc <<<8192 + 10240, 256>>>(x, Wo);
    prep_b1   <<<dim3(32, 120), dim3(32, 8)>>>(Wq, Wk, Wv, Ws, Wd);
    gemm1     <<<dim3(58, 16), 256, GEMM1_SMEM>>>();
    route_pack<<<16 * 512 * 64 / 256, 256>>>();
    attn_tc   <<<dim3(8, 16), 256, ATTN_SMEM>>>();
    gemm2     <<<dim3(N2 / 64, BT / 128), 256, GEMM2_SMEM>>>(out);
}

// round 15
// speedup vs baseline: 1.4462x; 1.0310x over previous
#include <cuda_runtime.h>
#include <cuda_fp16.h>
#include <cstdint>

#define Tt   1024
#define DIMD 1024
#define Hh   8
#define Ee   5
#define KK   3
#define BT   2048
#define HS   512
#define HE   40
#define QSCALE 0.125f

#define N1 3840
#define N2 1024
#define V2 2560

// ---------------- scratch ----------------------------------------------------
__device__ float g_C1 [BT * N1];          // only SsSd cols (3584+) used now
__device__ __half g_Vf[(size_t)BT * V2];  // V projection output, fp16
// fp16 blob for gemm1: A(hi,lo), B(hi) all rows, B(lo) for SsSd rows
#define A1Hf 0
#define A1Lf (BT * 1024)
#define B1Hf (2 * BT * 1024)
#define B1Lf (2 * BT * 1024 + N1 * 1024)
__device__ __half g_W1f[2 * BT * 1024 + 2 * N1 * 1024];
// fp16 blob for gemm2 (plain 1-term)
#define A2H 0
#define B2H (BT * V2)
__device__ __half g_W2[BT * V2 + N2 * V2];

__device__ float g_sdg[BT * HE];
// attention operands: packed fp16x2 pairs
__device__ uint32_t g_Qh[16 * 1024 * 32];   // [bh][t][dpair]
__device__ uint32_t g_Ql[16 * 1024 * 32];
__device__ uint32_t g_Kh[16 * 1024 * 32];   // single-rounded fp16
__device__ uint32_t g_Vh[16 * 64 * 512];    // [bh][d][tpair], single-rounded fp16

// ---------------- helpers -----------------------------------------------------
__device__ __forceinline__ uint32_t smem_u32(const void* p) {
    uint32_t a;
    asm("{ .reg .u64 t; cvta.to.shared.u64 t, %1; cvt.u32.u64 %0, t; }" : "=r"(a) : "l"(p));
    return a;
}
__device__ __forceinline__ void cpasync16(uint32_t dst, const void* src) {
    asm volatile("cp.async.cg.shared.global [%0], [%1], 16;\n" :: "r"(dst), "l"(src));
}
__device__ __forceinline__ void cp_commit() { asm volatile("cp.async.commit_group;\n"); }
template<int N> __device__ __forceinline__ void cp_wait() { asm volatile("cp.async.wait_group %0;\n" :: "n"(N)); }

__device__ __forceinline__ void mma16816f(float* c, const uint32_t* a, const uint32_t* b) {
    asm volatile(
        "mma.sync.aligned.m16n8k16.row.col.f32.f16.f16.f32 "
        "{%0,%1,%2,%3}, {%4,%5,%6,%7}, {%8,%9}, {%0,%1,%2,%3};"
        : "+f"(c[0]), "+f"(c[1]), "+f"(c[2]), "+f"(c[3])
        : "r"(a[0]), "r"(a[1]), "r"(a[2]), "r"(a[3]), "r"(b[0]), "r"(b[1]));
}
__device__ __forceinline__ void ldm_x4(uint32_t* r, uint32_t addr) {
    asm volatile("ldmatrix.sync.aligned.m8n8.x4.shared.b16 {%0,%1,%2,%3}, [%4];"
        : "=r"(r[0]), "=r"(r[1]), "=r"(r[2]), "=r"(r[3]) : "r"(addr));
}
__device__ __forceinline__ uint32_t packh2(float lo, float hi) {
    __half2 h = __floats2half2_rn(lo, hi);
    return *(uint32_t*)&h;
}
__device__ __forceinline__ uint32_t packh2res(uint32_t p, float lo, float hi) {
    __half2 ph = *(__half2*)&p;
    float2 bk = __half22float2(ph);
    return packh2(lo - bk.x, hi - bk.y);
}
#define WGBAR(id) asm volatile("bar.sync %0, 128;" :: "r"((id) + 1) : "memory")

// ---------------- fp16 GEMM, configurable split terms ------------------------
// C = Ah@Bh^T (+ Al@Bh^T if ASPLIT) (+ Ah@Bl^T if BSPLIT)
// FUSEQK: tiles n0<1024 write fp16 Q(split)/K(rounded) pair arrays.
// VOUT: write fp16 packed output to g_Vf at column (n0-1024).
template<int NT, int KTOT, bool FUSEQK, bool VOUT, bool ASPLIT, bool BSPLIT>
__device__ __forceinline__ void gemmf_body(const char* __restrict__ W,
                                           uint32_t offAh, uint32_t offAl,
                                           uint32_t offBh, uint32_t offBl,
                                           float* __restrict__ C, int Ntot)
{
    constexpr int AR    = ASPLIT ? 256 : 128;
    constexpr int AC    = ASPLIT ? 4 : 2;
    constexpr int ROWS  = AR + (BSPLIT ? 2 : 1) * NT;
    constexpr int STAGE = ROWS * 64;
    constexpr int NSTEP = KTOT / 32;
    constexpr int NTW   = NT / 2;
    constexpr int NPAIR = NTW / 16;
    constexpr int NA    = NTW / 8;
    constexpr int CPT   = ROWS / 64;
    constexpr int NB    = NT / 64;
    constexpr size_t K2B = KTOT * 2;

    extern __shared__ char sm_raw[];
    const uint32_t sb = smem_u32(sm_raw);
    const int tid = threadIdx.x, wid = tid >> 5, lane = tid & 31;
    const int wm = wid & 3, wn = wid >> 2;
    const int m0 = blockIdx.y * 128, n0 = blockIdx.x * NT;

    const int r0 = tid >> 2;
    const int cc = (tid & 3) * 16;
    const uint32_t dst0 = r0 * 64 + (cc ^ (((r0 >> 1) & 3) * 16));
    const char* pAh = W + offAh + (size_t)(m0 + r0) * K2B + cc;
    const char* pAl = W + offAl + (size_t)(m0 + r0) * K2B + cc;
    const char* pBh = W + offBh + (size_t)(n0 + r0) * K2B + cc;
    const char* pBl = W + offBl + (size_t)(n0 + r0) * K2B + cc;

    auto issue = [&](int kt, int slot) {
        const uint32_t st = sb + slot * STAGE + dst0;
        const size_t gk = (size_t)kt * 64;
#pragma unroll
        for (int i = 0; i < CPT; i++) {
            const char* src;
            if      (i < 2)            src = pAh + (size_t)i * (64 * K2B);
            else if (ASPLIT && i < AC) src = pAl + (size_t)(i - 2) * (64 * K2B);
            else if (i < AC + NB)      src = pBh + (size_t)(i - AC) * (64 * K2B);
            else                       src = pBl + (size_t)(i - AC - NB) * (64 * K2B);
            cpasync16(st + i * 4096, src + gk);
        }
    };

    const uint32_t ahi = (lane >> 4) * 16;
    const uint32_t bhi = ((lane >> 3) & 1) * 16;
    uint32_t aof[2], aswz[2], bof[NPAIR], bswz[NPAIR];
#pragma unroll
    for (int mi = 0; mi < 2; mi++) {
        int r = wm * 32 + mi * 16 + (lane & 15);
        aof[mi] = r * 64; aswz[mi] = ((r >> 1) & 3) * 16;
    }
#pragma unroll
    for (int pj = 0; pj < NPAIR; pj++) {
        int r = wn * NTW + pj * 16 + ((lane >> 4) << 3) + (lane & 7);
        bof[pj] = (AR + r) * 64; bswz[pj] = ((r >> 1) & 3) * 16;
    }

    float acc[2][NA][4];
#pragma unroll
    for (int mi = 0; mi < 2; mi++)
#pragma unroll
        for (int na = 0; na < NA; na++)
#pragma unroll
            for (int q = 0; q < 4; q++) acc[mi][na][q] = 0.f;

    issue(0, 0); cp_commit();
    issue(1, 1); cp_commit();

    for (int kt = 0; kt < NSTEP; kt++) {
        if (kt + 1 < NSTEP) cp_wait<1>(); else cp_wait<0>();
        __syncthreads();
        if (kt + 2 < NSTEP) { issue(kt + 2, (kt + 2) % 3); cp_commit(); }

        uint32_t stg = sb + (kt % 3) * STAGE;
#pragma unroll
        for (int ks = 0; ks < 2; ks++) {
            const uint32_t ca = (uint32_t)ks * 32 + ahi;
            const uint32_t cb = (uint32_t)ks * 32 + bhi;
            uint32_t ah[2][4], al[2][4], bb[NPAIR][4];
            ldm_x4(ah[0], stg + aof[0] + (ca ^ aswz[0]));
            ldm_x4(ah[1], stg + aof[1] + (ca ^ aswz[1]));
            if (ASPLIT) {
                ldm_x4(al[0], stg + 8192 + aof[0] + (ca ^ aswz[0]));
                ldm_x4(al[1], stg + 8192 + aof[1] + (ca ^ aswz[1]));
            }
#pragma unroll
            for (int pj = 0; pj < NPAIR; pj++)
                ldm_x4(bb[pj], stg + bof[pj] + (cb ^ bswz[pj]));
#pragma unroll
            for (int mi = 0; mi < 2; mi++)
#pragma unroll
                for (int pj = 0; pj < NPAIR; pj++) {
                    mma16816f(acc[mi][2 * pj],     ah[mi], &bb[pj][0]);
                    mma16816f(acc[mi][2 * pj + 1], ah[mi], &bb[pj][2]);
                }
            if (ASPLIT) {
#pragma unroll
                for (int mi = 0; mi < 2; mi++)
#pragma unroll
                    for (int pj = 0; pj < NPAIR; pj++) {
                        mma16816f(acc[mi][2 * pj],     al[mi], &bb[pj][0]);
                        mma16816f(acc[mi][2 * pj + 1], al[mi], &bb[pj][2]);
                    }
            }
            if (BSPLIT) {
#pragma unroll
                for (int pj = 0; pj < NPAIR; pj++)
                    ldm_x4(bb[pj], stg + bof[pj] + NT * 64 + (cb ^ bswz[pj]));
#pragma unroll
                for (int mi = 0; mi < 2; mi++)
#pragma unroll
                    for (int pj = 0; pj < NPAIR; pj++) {
                        mma16816f(acc[mi][2 * pj],     ah[mi], &bb[pj][0]);
                        mma16816f(acc[mi][2 * pj + 1], ah[mi], &bb[pj][2]);
                    }
            }
        }
    }

    const int g  = lane >> 2;
    const int tg = lane & 3;

    if (FUSEQK && n0 < 1024) {
        const bool isQ = (n0 < 512);
        const float sc = isQ ? QSCALE : 1.0f;
#pragma unroll
        for (int mi = 0; mi < 2; mi++) {
            int r = m0 + wm * 32 + mi * 16 + g;
            int b_ = r >> 10, t = r & 1023;
#pragma unroll
            for (int na = 0; na < NA; na++) {
                int ccc = n0 + wn * NTW + na * 8 + tg * 2;
                int h = (ccc >> 6) & 7;
                int p = (ccc & 63) >> 1;
                size_t base = (((size_t)(b_ * 8 + h) << 10) + t) * 32 + p;
                float v0 = acc[mi][na][0] * sc, v1 = acc[mi][na][1] * sc;
                float w0 = acc[mi][na][2] * sc, w1 = acc[mi][na][3] * sc;
                uint32_t h0 = packh2(v0, v1);
                uint32_t h1 = packh2(w0, w1);
                if (isQ) {
                    g_Qh[base] = h0; g_Ql[base] = packh2res(h0, v0, v1);
                    g_Qh[base + 8 * 32] = h1; g_Ql[base + 8 * 32] = packh2res(h1, w0, w1);
                } else {
                    g_Kh[base] = h0;
                    g_Kh[base + 8 * 32] = h1;
                }
            }
        }
    } else if (VOUT) {
#pragma unroll
        for (int mi = 0; mi < 2; mi++) {
            int r = m0 + wm * 32 + mi * 16 + g;
#pragma unroll
            for (int na = 0; na < NA; na++) {
                int vc = n0 - 1024 + wn * NTW + na * 8 + tg * 2;
                *(uint32_t*)((__half*)g_Vf + (size_t)r * V2 + vc) =
                    packh2(acc[mi][na][0], acc[mi][na][1]);
                *(uint32_t*)((__half*)g_Vf + (size_t)(r + 8) * V2 + vc) =
                    packh2(acc[mi][na][2], acc[mi][na][3]);
            }
        }
    } else {
#pragma unroll
        for (int mi = 0; mi < 2; mi++) {
            int r = m0 + wm * 32 + mi * 16 + g;
#pragma unroll
            for (int na = 0; na < NA; na++) {
                int ccc = n0 + wn * NTW + na * 8 + tg * 2;
                *(float2*)(C + (size_t)r * Ntot + ccc)       = make_float2(acc[mi][na][0], acc[mi][na][1]);
                *(float2*)(C + (size_t)(r + 8) * Ntot + ccc) = make_float2(acc[mi][na][2], acc[mi][na][3]);
            }
        }
    }
}

#define GEMM1_SMEM (3 * (256 + 128) * 64)   // 73728 (3-term NT=64 worst case)
#define GEMM2_SMEM (3 * (128 + 64) * 64)    // 36864

__global__ __launch_bounds__(256, 3)
void gemm1() {
    if (blockIdx.x < 16)       // Q (0-7) + K (8-15), fused epilogue, 2-term
        gemmf_body<64, 1024, true,  false, true,  false>((const char*)g_W1f, A1Hf*2, A1Lf*2, B1Hf*2, B1Lf*2, g_C1, N1);
    else if (blockIdx.x < 56)  // V tiles: plain fp16 1-term -> g_Vf
        gemmf_body<64, 1024, false, true,  false, false>((const char*)g_W1f, A1Hf*2, A1Lf*2, B1Hf*2, B1Lf*2, g_C1, N1);
    else                       // SsSd tiles (56,57): fp16 3-term (near-fp32)
        gemmf_body<64, 1024, false, false, true,  true >((const char*)g_W1f, A1Hf*2, A1Lf*2, B1Hf*2, B1Lf*2, g_C1, N1);
}
__global__ __launch_bounds__(256, 3)
void gemm2(float* __restrict__ out) {
    gemmf_body<64, 2560, false, false, false, false>((const char*)g_W2, A2H*2, 0, B2H*2, 0, out, N2);
}

// ---------------- prep kernels ----------------------------------------------
__global__ __launch_bounds__(256) void prep_misc(const float* __restrict__ x,
                                                 const float* __restrict__ Wo) {
    int bid = blockIdx.x;
    if (bid < 8192) {
        int gid = bid * 256 + threadIdx.x;
        float v = x[gid];
        __half fh = __float2half_rn(v);
        __half fl = __float2half_rn(v - __half2float(fh));
        g_W1f[A1Hf + gid] = fh;
        g_W1f[A1Lf + gid] = fl;
    } else {
        int gid = (bid - 8192) * 256 + threadIdx.x;
        int he = gid >> 16;
        int d  = (gid >> 6) & 1023;
        int c  = gid & 63;
        g_W2[B2H + d * V2 + he * 64 + c] = __float2half_rn(Wo[gid]);
    }
}

__global__ void prep_b1(const float* __restrict__ Wq, const float* __restrict__ Wk,
                        const float* __restrict__ Wv, const float* __restrict__ Ws,
                        const float* __restrict__ Wd)
{
    __shared__ float tile[32][33];
    int k0 = blockIdx.x * 32;
    int n0 = blockIdx.y * 32;
    int tx = threadIdx.x, ty = threadIdx.y;
#pragma unroll
    for (int yy = 0; yy < 32; yy += 8) {
        int k = k0 + ty + yy, n = n0 + tx;
        float w;
        if      (n < 512)  w = Wq[(size_t)k * 512  + n];
        else if (n < 1024) w = Wk[(size_t)k * 512  + n - 512];
        else if (n < 3584) w = Wv[(size_t)k * 2560 + n - 1024];
        else if (n < 3624) w = Ws[(size_t)k * 40   + n - 3584];
        else if (n < 3664) w = Wd[(size_t)k * 40   + n - 3624];
        else               w = 0.f;
        tile[ty + yy][tx] = w;
    }
    __syncthreads();
#pragma unroll
    for (int yy = 0; yy < 32; yy += 8) {
        int n = n0 + ty + yy, k = k0 + tx;
        float w = tile[tx][ty + yy];
        int idx = n * 1024 + k;
        __half fh = __float2half_rn(w);
        g_W1f[B1Hf + idx] = fh;
        if (n >= 3584)
            g_W1f[B1Lf + idx] = __float2half_rn(w - __half2float(fh));
    }
}

// ---------------- fused routing gates + expert V mix + transposed pack -------
__global__ __launch_bounds__(256) void route_pack() {
    __shared__ uint32_t tvh[4][65];
    int gid = blockIdx.x * 256 + threadIdx.x;
    int d  = gid & 63;
    int kp = (gid >> 6) & 511;
    int bh = gid >> 15;
    int b = bh >> 3, h = bh & 7;

    float v[2];
#pragma unroll
    for (int u = 0; u < 2; u++) {
        int t = kp * 2 + u;
        const float* row = g_C1 + (size_t)(b * 1024 + t) * N1;
        const __half* vrow = (const __half*)g_Vf + (size_t)(b * 1024 + t) * V2;
        const float* sl = row + 3584 + h * Ee;
        float s[Ee];
#pragma unroll
        for (int e = 0; e < Ee; e++) s[e] = sl[e];
        float acc = 0.f;
#pragma unroll
        for (int e = 0; e < Ee; e++) {
            int rank = 0;
#pragma unroll
            for (int j = 0; j < Ee; j++)
                rank += (s[j] > s[e]) || (s[j] == s[e] && j < e);
            float gate = (rank < KK) ? 1.0f / (1.0f + expf(-s[e])) : 0.f;
            acc = fmaf(gate, __half2float(vrow[(h * Ee + e) * 64 + d]), acc);
        }
        v[u] = acc;

        if (d < Ee) {
            const float* dl = row + 3624 + h * Ee;
            float tq[Ee];
#pragma unroll
            for (int e = 0; e < Ee; e++) tq[e] = dl[e];
            int e = d, rank = 0;
#pragma unroll
            for (int j = 0; j < Ee; j++)
                rank += (tq[j] > tq[e]) || (tq[j] == tq[e] && j < e);
            g_sdg[(b * 1024 + t) * HE + h * Ee + e] = (rank < KK) ? 1.f : 0.f;
        }
    }
    tvh[kp & 3][d] = packh2(v[0], v[1]);
    __syncthreads();
    int td  = threadIdx.x >> 2;
    int tk4 = threadIdx.x & 3;
    int kp0 = (blockIdx.x * 4) & 511;
    g_Vh[((size_t)bh * 64 + td) * 512 + kp0 + tk4] = tvh[tk4][td];
}

// ---------------- tensor-core causal flash attention -------------------------
// S = (Qh+Ql)*Kh ; O += Ph*Vh (Pl residual dropped).
#define AQS   (64 * 36)
#define ATL   (64 * 36)
#define ASTG  (2 * ATL)
#define AWG_U (2 * AQS + 2 * ASTG)
#define ATTN_SMEM (2 * AWG_U * 4)

__global__ __launch_bounds__(256) void attn_tc() {
    extern __shared__ uint32_t sm[];
    const int bh   = blockIdx.y;
    const int b    = bh >> 3, h = bh & 7;
    const int wg   = threadIdx.x >> 7;
    const int qt   = wg ? (15 - blockIdx.x) : blockIdx.x;
    const int tid  = threadIdx.x & 127;
    const int w    = tid >> 5;
    const int lane = tid & 31;
    const int g    = lane >> 2;
    const int tig  = lane & 3;
    uint32_t* smg  = sm + wg * AWG_U;
    const uint32_t sb = smem_u32(smg);

    auto issue = [&](int kt, int s) {
#pragma unroll
        for (int i = 0; i < 8; i++) {
            int a = i >> 2;
            int r = (i & 3) * 16 + (tid >> 3);
            int c = tid & 7;
            uint32_t dst = sb + (2 * AQS + s * ASTG + a * ATL + r * 36) * 4 + c * 16;
            const uint32_t* srcb;
            if (a == 0) srcb = g_Kh + ((size_t)(bh << 10) + kt * 64 + r) * 32;
            else        srcb = g_Vh + ((size_t)bh * 64 + r) * 512 + kt * 32;
            cpasync16(dst, (const char*)srcb + c * 16);
        }
    };
    issue(0, 0); cp_commit();

    {
        const uint32_t* qhsrc = g_Qh + ((size_t)(bh << 10) + qt * 64) * 32;
        const uint32_t* qlsrc = g_Ql + ((size_t)(bh << 10) + qt * 64) * 32;
#pragma unroll
        for (int j = 0; j < 4; j++) {
            int idx = tid + j * 128;
            int row = idx >> 3, po = (idx & 7) * 4;
            *(uint4*)&smg[row * 36 + po]       = *(const uint4*)(qhsrc + row * 32 + po);
            *(uint4*)&smg[AQS + row * 36 + po] = *(const uint4*)(qlsrc + row * 32 + po);
        }
    }
    WGBAR(wg);

    uint32_t qa[2][4][4];
#pragma unroll
    for (int hl = 0; hl < 2; hl++) {
        int qb = hl * AQS;
#pragma unroll
        for (int kb = 0; kb < 4; kb++) {
            qa[hl][kb][0] = smg[qb + (w * 16 + g)     * 36 + kb * 8 + tig];
            qa[hl][kb][1] = smg[qb + (w * 16 + g + 8) * 36 + kb * 8 + tig];
            qa[hl][kb][2] = smg[qb + (w * 16 + g)     * 36 + kb * 8 + 4 + tig];
            qa[hl][kb][3] = smg[qb + (w * 16 + g + 8) * 36 + kb * 8 + 4 + tig];
        }
    }

    const int li   = lane >> 3;
    const uint32_t lbase = (((li >> 1) * 8 + (lane & 7)) * 36 + (li & 1) * 4) * 4;

    float o[8][4];
#pragma unroll
    for (int a = 0; a < 8; a++)
#pragma unroll
        for (int q = 0; q < 4; q++) o[a][q] = 0.f;
    float m[2] = {-1e30f, -1e30f}, l[2] = {0.f, 0.f};

    for (int kt = 0; kt <= qt; kt++) {
        if (kt < qt) { issue(kt + 1, (kt + 1) & 1); cp_commit(); cp_wait<1>(); }
        else         { cp_wait<0>(); }
        WGBAR(wg);

        const uint32_t su  = sb + (2 * AQS + (kt & 1) * ASTG) * 4;
        const uint32_t Khb = su, Vhb = su + ATL * 4;

        float s[8][4];
#pragma unroll
        for (int a = 0; a < 8; a++)
#pragma unroll
            for (int q = 0; q < 4; q++) s[a][q] = 0.f;

#pragma unroll
        for (int kb = 0; kb < 4; kb++) {
            uint32_t bb[4][4];
#pragma unroll
            for (int j = 0; j < 4; j++)
                ldm_x4(bb[j], Khb + lbase + (j * 576 + kb * 8) * 4);
#pragma unroll
            for (int j = 0; j < 4; j++) {
                mma16816f(s[2*j],   qa[0][kb], &bb[j][0]);
                mma16816f(s[2*j+1], qa[0][kb], &bb[j][2]);
            }
#pragma unroll
            for (int j = 0; j < 4; j++) {
                mma16816f(s[2*j],   qa[1][kb], &bb[j][0]);
                mma16816f(s[2*j+1], qa[1][kb], &bb[j][2]);
            }
        }

        if (kt == qt) {
            int r0 = w * 16 + g;
#pragma unroll
            for (int na = 0; na < 8; na++) {
                int c0 = na * 8 + 2 * tig;
                if (c0     > r0)     s[na][0] = -1e9f;
                if (c0 + 1 > r0)     s[na][1] = -1e9f;
                if (c0     > r0 + 8) s[na][2] = -1e9f;
                if (c0 + 1 > r0 + 8) s[na][3] = -1e9f;
            }
        }

#pragma unroll
        for (int ri = 0; ri < 2; ri++) {
            float mx = -1e30f;
#pragma unroll
            for (int a = 0; a < 8; a++)
                mx = fmaxf(mx, fmaxf(s[a][2 * ri], s[a][2 * ri + 1]));
            mx = fmaxf(mx, __shfl_xor_sync(0xffffffffu, mx, 1));
            mx = fmaxf(mx, __shfl_xor_sync(0xffffffffu, mx, 2));
            float mnew = fmaxf(m[ri], mx);
            float corr = __expf(m[ri] - mnew);
            float rs = 0.f;
#pragma unroll
            for (int a = 0; a < 8; a++) {
                float p0 = __expf(s[a][2 * ri]     - mnew);
                float p1 = __expf(s[a][2 * ri + 1] - mnew);
                s[a][2 * ri] = p0; s[a][2 * ri + 1] = p1;
                rs += p0 + p1;
            }
            rs += __shfl_xor_sync(0xffffffffu, rs, 1);
            rs += __shfl_xor_sync(0xffffffffu, rs, 2);
            l[ri] = l[ri] * corr + rs;
            m[ri] = mnew;
#pragma unroll
            for (int a = 0; a < 8; a++) { o[a][2 * ri] *= corr; o[a][2 * ri + 1] *= corr; }
        }

        // ---- O += Ph * Vh ----
#pragma unroll
        for (int kb = 0; kb < 4; kb++) {
            uint32_t ph[4];
            ph[0] = packh2(s[2*kb][0],   s[2*kb][1]);
            ph[1] = packh2(s[2*kb][2],   s[2*kb][3]);
            ph[2] = packh2(s[2*kb+1][0], s[2*kb+1][1]);
            ph[3] = packh2(s[2*kb+1][2], s[2*kb+1][3]);

            uint32_t bb[4][4];
#pragma unroll
            for (int j = 0; j < 4; j++)
                ldm_x4(bb[j], Vhb + lbase + (j * 576 + kb * 8) * 4);
#pragma unroll
            for (int j = 0; j < 4; j++) {
                mma16816f(o[2*j],   ph, &bb[j][0]);
                mma16816f(o[2*j+1], ph, &bb[j][2]);
            }
        }
        WGBAR(wg);
    }

    // ---- fused epilogue: A2 = fp16(sd * O) for all 5 experts ----
    float inv0 = 1.0f / l[0], inv1 = 1.0f / l[1];
    int row0 = qt * 64 + w * 16 + g;
    int bt0  = b * 1024 + row0;

    float g0[Ee], g1[Ee];
#pragma unroll
    for (int e = 0; e < Ee; e++) {
        g0[e] = g_sdg[bt0 * HE + h * Ee + e];
        g1[e] = g_sdg[(bt0 + 8) * HE + h * Ee + e];
    }
    uint32_t* a2h0 = (uint32_t*)(g_W2 + A2H + (size_t)bt0 * V2);
    uint32_t* a2h1 = (uint32_t*)(g_W2 + A2H + (size_t)(bt0 + 8) * V2);

#pragma unroll
    for (int na = 0; na < 8; na++) {
        int c0 = na * 8 + 2 * tig;
        float v00 = o[na][0] * inv0, v01 = o[na][1] * inv0;
        float v10 = o[na][2] * inv1, v11 = o[na][3] * inv1;
        uint32_t h0u = packh2(v00, v01);
        uint32_t h1u = packh2(v10, v11);
#pragma unroll
        for (int e = 0; e < Ee; e++) {
            int cw = ((h * Ee + e) * 64 + c0) >> 1;
            a2h0[cw] = (g0[e] != 0.f) ? h0u : 0u;
            a2h1[cw] = (g1[e] != 0.f) ? h1u : 0u;
        }
    }
}

// ---------------- launch ------------------------------------------------------
extern "C" void kernel_launch(void* const* d_in, const int* in_sizes, int n_in,
                              void* d_out, int out_size)
{
    const float* x  = (const float*)d_in[0];
    const float* Wq = (const float*)d_in[1];
    const float* Wk = (const float*)d_in[2];
    const float* Wv = (const float*)d_in[3];
    const float* Ws = (const float*)d_in[4];
    const float* Wd = (const float*)d_in[5];
    const float* Wo = (const float*)d_in[6];
    float* out = (float*)d_out;

    cudaFuncSetAttribute(gemm1,   cudaFuncAttributeMaxDynamicSharedMemorySize, GEMM1_SMEM);
    cudaFuncSetAttribute(gemm2,   cudaFuncAttributeMaxDynamicSharedMemorySize, GEMM2_SMEM);
    cudaFuncSetAttribute(attn_tc, cudaFuncAttributeMaxDynamicSharedMemorySize, ATTN_SMEM);

    prep_misc <<<8192 + 10240, 256>>>(x, Wo);
    prep_b1   <<<dim3(32, 120), dim3(32, 8)>>>(Wq, Wk, Wv, Ws, Wd);
    gemm1     <<<dim3(58, 16), 256, GEMM1_SMEM>>>();
    route_pack<<<16 * 512 * 64 / 256, 256>>>();
    attn_tc   <<<dim3(8, 16), 256, ATTN_SMEM>>>();
    gemm2     <<<dim3(N2 / 64, BT / 128), 256, GEMM2_SMEM>>>(out);
}

// round 16
// speedup vs baseline: 1.5366x; 1.0625x over previous
#include <cuda_runtime.h>
#include <cuda_fp16.h>
#include <cstdint>

#define Tt   1024
#define DIMD 1024
#define Hh   8
#define Ee   5
#define KK   3
#define BT   2048
#define HS   512
#define HE   40
#define QSCALE 0.125f

#define N1 3840
#define N2 1024
#define V2 2560

// ---------------- scratch ----------------------------------------------------
__device__ float g_C1 [BT * N1];          // only SsSd cols (3584+) used
__device__ __half g_Vf[(size_t)BT * V2];  // V projection output, fp16
#define A1Hf 0
#define A1Lf (BT * 1024)
#define B1Hf (2 * BT * 1024)
#define B1Lf (2 * BT * 1024 + N1 * 1024)
__device__ __half g_W1f[2 * BT * 1024 + 2 * N1 * 1024];
#define A2H 0
#define B2H (BT * V2)
__device__ __half g_W2[BT * V2 + N2 * V2];

__device__ float g_gate[BT * HE];   // soft source gates
__device__ float g_sdg [BT * HE];   // 0/1 dest gates
// attention operands: packed fp16x2 pairs (all single-rounded fp16)
__device__ uint32_t g_Qh[16 * 1024 * 32];   // [bh][t][dpair]
__device__ uint32_t g_Kh[16 * 1024 * 32];
__device__ uint32_t g_Vh[16 * 64 * 512];    // [bh][d][tpair]

// ---------------- helpers -----------------------------------------------------
__device__ __forceinline__ uint32_t smem_u32(const void* p) {
    uint32_t a;
    asm("{ .reg .u64 t; cvta.to.shared.u64 t, %1; cvt.u32.u64 %0, t; }" : "=r"(a) : "l"(p));
    return a;
}
__device__ __forceinline__ void cpasync16(uint32_t dst, const void* src) {
    asm volatile("cp.async.cg.shared.global [%0], [%1], 16;\n" :: "r"(dst), "l"(src));
}
__device__ __forceinline__ void cp_commit() { asm volatile("cp.async.commit_group;\n"); }
template<int N> __device__ __forceinline__ void cp_wait() { asm volatile("cp.async.wait_group %0;\n" :: "n"(N)); }

__device__ __forceinline__ void mma16816f(float* c, const uint32_t* a, const uint32_t* b) {
    asm volatile(
        "mma.sync.aligned.m16n8k16.row.col.f32.f16.f16.f32 "
        "{%0,%1,%2,%3}, {%4,%5,%6,%7}, {%8,%9}, {%0,%1,%2,%3};"
        : "+f"(c[0]), "+f"(c[1]), "+f"(c[2]), "+f"(c[3])
        : "r"(a[0]), "r"(a[1]), "r"(a[2]), "r"(a[3]), "r"(b[0]), "r"(b[1]));
}
__device__ __forceinline__ void ldm_x4(uint32_t* r, uint32_t addr) {
    asm volatile("ldmatrix.sync.aligned.m8n8.x4.shared.b16 {%0,%1,%2,%3}, [%4];"
        : "=r"(r[0]), "=r"(r[1]), "=r"(r[2]), "=r"(r[3]) : "r"(addr));
}
__device__ __forceinline__ uint32_t packh2(float lo, float hi) {
    __half2 h = __floats2half2_rn(lo, hi);
    return *(uint32_t*)&h;
}
__device__ __forceinline__ uint32_t packh2res(uint32_t p, float lo, float hi) {
    __half2 ph = *(__half2*)&p;
    float2 bk = __half22float2(ph);
    return packh2(lo - bk.x, hi - bk.y);
}
#define WGBAR(id) asm volatile("bar.sync %0, 128;" :: "r"((id) + 1) : "memory")

// ---------------- fp16 GEMM, configurable split terms ------------------------
template<int NT, int KTOT, bool FUSEQK, bool VOUT, bool ASPLIT, bool BSPLIT>
__device__ __forceinline__ void gemmf_body(const char* __restrict__ W,
                                           uint32_t offAh, uint32_t offAl,
                                           uint32_t offBh, uint32_t offBl,
                                           float* __restrict__ C, int Ntot)
{
    constexpr int AR    = ASPLIT ? 256 : 128;
    constexpr int AC    = ASPLIT ? 4 : 2;
    constexpr int ROWS  = AR + (BSPLIT ? 2 : 1) * NT;
    constexpr int STAGE = ROWS * 64;
    constexpr int NSTEP = KTOT / 32;
    constexpr int NTW   = NT / 2;
    constexpr int NPAIR = NTW / 16;
    constexpr int NA    = NTW / 8;
    constexpr int CPT   = ROWS / 64;
    constexpr int NB    = NT / 64;
    constexpr size_t K2B = KTOT * 2;

    extern __shared__ char sm_raw[];
    const uint32_t sb = smem_u32(sm_raw);
    const int tid = threadIdx.x, wid = tid >> 5, lane = tid & 31;
    const int wm = wid & 3, wn = wid >> 2;
    const int m0 = blockIdx.y * 128, n0 = blockIdx.x * NT;

    const int r0 = tid >> 2;
    const int cc = (tid & 3) * 16;
    const uint32_t dst0 = r0 * 64 + (cc ^ (((r0 >> 1) & 3) * 16));
    const char* pAh = W + offAh + (size_t)(m0 + r0) * K2B + cc;
    const char* pAl = W + offAl + (size_t)(m0 + r0) * K2B + cc;
    const char* pBh = W + offBh + (size_t)(n0 + r0) * K2B + cc;
    const char* pBl = W + offBl + (size_t)(n0 + r0) * K2B + cc;

    auto issue = [&](int kt, int slot) {
        const uint32_t st = sb + slot * STAGE + dst0;
        const size_t gk = (size_t)kt * 64;
#pragma unroll
        for (int i = 0; i < CPT; i++) {
            const char* src;
            if      (i < 2)            src = pAh + (size_t)i * (64 * K2B);
            else if (ASPLIT && i < AC) src = pAl + (size_t)(i - 2) * (64 * K2B);
            else if (i < AC + NB)      src = pBh + (size_t)(i - AC) * (64 * K2B);
            else                       src = pBl + (size_t)(i - AC - NB) * (64 * K2B);
            cpasync16(st + i * 4096, src + gk);
        }
    };

    const uint32_t ahi = (lane >> 4) * 16;
    const uint32_t bhi = ((lane >> 3) & 1) * 16;
    uint32_t aof[2], aswz[2], bof[NPAIR], bswz[NPAIR];
#pragma unroll
    for (int mi = 0; mi < 2; mi++) {
        int r = wm * 32 + mi * 16 + (lane & 15);
        aof[mi] = r * 64; aswz[mi] = ((r >> 1) & 3) * 16;
    }
#pragma unroll
    for (int pj = 0; pj < NPAIR; pj++) {
        int r = wn * NTW + pj * 16 + ((lane >> 4) << 3) + (lane & 7);
        bof[pj] = (AR + r) * 64; bswz[pj] = ((r >> 1) & 3) * 16;
    }

    float acc[2][NA][4];
#pragma unroll
    for (int mi = 0; mi < 2; mi++)
#pragma unroll
        for (int na = 0; na < NA; na++)
#pragma unroll
            for (int q = 0; q < 4; q++) acc[mi][na][q] = 0.f;

    issue(0, 0); cp_commit();
    issue(1, 1); cp_commit();

    for (int kt = 0; kt < NSTEP; kt++) {
        if (kt + 1 < NSTEP) cp_wait<1>(); else cp_wait<0>();
        __syncthreads();
        if (kt + 2 < NSTEP) { issue(kt + 2, (kt + 2) % 3); cp_commit(); }

        uint32_t stg = sb + (kt % 3) * STAGE;
#pragma unroll
        for (int ks = 0; ks < 2; ks++) {
            const uint32_t ca = (uint32_t)ks * 32 + ahi;
            const uint32_t cb = (uint32_t)ks * 32 + bhi;
            uint32_t ah[2][4], al[2][4], bb[NPAIR][4];
            ldm_x4(ah[0], stg + aof[0] + (ca ^ aswz[0]));
            ldm_x4(ah[1], stg + aof[1] + (ca ^ aswz[1]));
            if (ASPLIT) {
                ldm_x4(al[0], stg + 8192 + aof[0] + (ca ^ aswz[0]));
                ldm_x4(al[1], stg + 8192 + aof[1] + (ca ^ aswz[1]));
            }
#pragma unroll
            for (int pj = 0; pj < NPAIR; pj++)
                ldm_x4(bb[pj], stg + bof[pj] + (cb ^ bswz[pj]));
#pragma unroll
            for (int mi = 0; mi < 2; mi++)
#pragma unroll
                for (int pj = 0; pj < NPAIR; pj++) {
                    mma16816f(acc[mi][2 * pj],     ah[mi], &bb[pj][0]);
                    mma16816f(acc[mi][2 * pj + 1], ah[mi], &bb[pj][2]);
                }
            if (ASPLIT) {
#pragma unroll
                for (int mi = 0; mi < 2; mi++)
#pragma unroll
                    for (int pj = 0; pj < NPAIR; pj++) {
                        mma16816f(acc[mi][2 * pj],     al[mi], &bb[pj][0]);
                        mma16816f(acc[mi][2 * pj + 1], al[mi], &bb[pj][2]);
                    }
            }
            if (BSPLIT) {
#pragma unroll
                for (int pj = 0; pj < NPAIR; pj++)
                    ldm_x4(bb[pj], stg + bof[pj] + NT * 64 + (cb ^ bswz[pj]));
#pragma unroll
                for (int mi = 0; mi < 2; mi++)
#pragma unroll
                    for (int pj = 0; pj < NPAIR; pj++) {
                        mma16816f(acc[mi][2 * pj],     ah[mi], &bb[pj][0]);
                        mma16816f(acc[mi][2 * pj + 1], ah[mi], &bb[pj][2]);
                    }
            }
        }
    }

    const int g  = lane >> 2;
    const int tg = lane & 3;

    if (FUSEQK && n0 < 1024) {
        const bool isQ = (n0 < 512);
        const float sc = isQ ? QSCALE : 1.0f;
        uint32_t* dh = isQ ? g_Qh : g_Kh;
#pragma unroll
        for (int mi = 0; mi < 2; mi++) {
            int r = m0 + wm * 32 + mi * 16 + g;
            int b_ = r >> 10, t = r & 1023;
#pragma unroll
            for (int na = 0; na < NA; na++) {
                int ccc = n0 + wn * NTW + na * 8 + tg * 2;
                int h = (ccc >> 6) & 7;
                int p = (ccc & 63) >> 1;
                size_t base = (((size_t)(b_ * 8 + h) << 10) + t) * 32 + p;
                dh[base]          = packh2(acc[mi][na][0] * sc, acc[mi][na][1] * sc);
                dh[base + 8 * 32] = packh2(acc[mi][na][2] * sc, acc[mi][na][3] * sc);
            }
        }
    } else if (VOUT) {
#pragma unroll
        for (int mi = 0; mi < 2; mi++) {
            int r = m0 + wm * 32 + mi * 16 + g;
#pragma unroll
            for (int na = 0; na < NA; na++) {
                int vc = n0 - 1024 + wn * NTW + na * 8 + tg * 2;
                *(uint32_t*)((__half*)g_Vf + (size_t)r * V2 + vc) =
                    packh2(acc[mi][na][0], acc[mi][na][1]);
                *(uint32_t*)((__half*)g_Vf + (size_t)(r + 8) * V2 + vc) =
                    packh2(acc[mi][na][2], acc[mi][na][3]);
            }
        }
    } else {
#pragma unroll
        for (int mi = 0; mi < 2; mi++) {
            int r = m0 + wm * 32 + mi * 16 + g;
#pragma unroll
            for (int na = 0; na < NA; na++) {
                int ccc = n0 + wn * NTW + na * 8 + tg * 2;
                *(float2*)(C + (size_t)r * Ntot + ccc)       = make_float2(acc[mi][na][0], acc[mi][na][1]);
                *(float2*)(C + (size_t)(r + 8) * Ntot + ccc) = make_float2(acc[mi][na][2], acc[mi][na][3]);
            }
        }
    }
}

#define GEMM1_SMEM (3 * (256 + 128) * 64)   // 73728
#define GEMM2_SMEM (3 * (128 + 64) * 64)    // 36864

__global__ __launch_bounds__(256, 3)
void gemm1() {
    if (blockIdx.x < 16)
        gemmf_body<64, 1024, true,  false, true,  false>((const char*)g_W1f, A1Hf*2, A1Lf*2, B1Hf*2, B1Lf*2, g_C1, N1);
    else if (blockIdx.x < 56)
        gemmf_body<64, 1024, false, true,  false, false>((const char*)g_W1f, A1Hf*2, A1Lf*2, B1Hf*2, B1Lf*2, g_C1, N1);
    else
        gemmf_body<64, 1024, false, false, true,  true >((const char*)g_W1f, A1Hf*2, A1Lf*2, B1Hf*2, B1Lf*2, g_C1, N1);
}
__global__ __launch_bounds__(256, 3)
void gemm2(float* __restrict__ out) {
    gemmf_body<64, 2560, false, false, false, false>((const char*)g_W2, A2H*2, 0, B2H*2, 0, out, N2);
}

// ---------------- prep kernels ----------------------------------------------
__global__ __launch_bounds__(256) void prep_misc(const float* __restrict__ x,
                                                 const float* __restrict__ Wo) {
    int bid = blockIdx.x;
    if (bid < 8192) {
        int gid = bid * 256 + threadIdx.x;
        float v = x[gid];
        __half fh = __float2half_rn(v);
        __half fl = __float2half_rn(v - __half2float(fh));
        g_W1f[A1Hf + gid] = fh;
        g_W1f[A1Lf + gid] = fl;
    } else {
        int gid = (bid - 8192) * 256 + threadIdx.x;
        int he = gid >> 16;
        int d  = (gid >> 6) & 1023;
        int c  = gid & 63;
        g_W2[B2H + d * V2 + he * 64 + c] = __float2half_rn(Wo[gid]);
    }
}

__global__ void prep_b1(const float* __restrict__ Wq, const float* __restrict__ Wk,
                        const float* __restrict__ Wv, const float* __restrict__ Ws,
                        const float* __restrict__ Wd)
{
    __shared__ float tile[32][33];
    int k0 = blockIdx.x * 32;
    int n0 = blockIdx.y * 32;
    int tx = threadIdx.x, ty = threadIdx.y;
#pragma unroll
    for (int yy = 0; yy < 32; yy += 8) {
        int k = k0 + ty + yy, n = n0 + tx;
        float w;
        if      (n < 512)  w = Wq[(size_t)k * 512  + n];
        else if (n < 1024) w = Wk[(size_t)k * 512  + n - 512];
        else if (n < 3584) w = Wv[(size_t)k * 2560 + n - 1024];
        else if (n < 3624) w = Ws[(size_t)k * 40   + n - 3584];
        else if (n < 3664) w = Wd[(size_t)k * 40   + n - 3624];
        else               w = 0.f;
        tile[ty + yy][tx] = w;
    }
    __syncthreads();
#pragma unroll
    for (int yy = 0; yy < 32; yy += 8) {
        int n = n0 + ty + yy, k = k0 + tx;
        float w = tile[tx][ty + yy];
        int idx = n * 1024 + k;
        __half fh = __float2half_rn(w);
        g_W1f[B1Hf + idx] = fh;
        if (n >= 3584)
            g_W1f[B1Lf + idx] = __float2half_rn(w - __half2float(fh));
    }
}

// ---------------- gates: one thread per (bt, h) ------------------------------
__global__ __launch_bounds__(256) void gates_k() {
    int gid = blockIdx.x * 256 + threadIdx.x;   // BT*H = 16384
    int h = gid & 7, bt = gid >> 3;
    const float* row = g_C1 + (size_t)bt * N1;
    const float* sl = row + 3584 + h * Ee;
    const float* dl = row + 3624 + h * Ee;
    float s[Ee], t[Ee];
#pragma unroll
    for (int e = 0; e < Ee; e++) { s[e] = sl[e]; t[e] = dl[e]; }
#pragma unroll
    for (int e = 0; e < Ee; e++) {
        int rs = 0, rd = 0;
#pragma unroll
        for (int j = 0; j < Ee; j++) {
            rs += (s[j] > s[e]) || (s[j] == s[e] && j < e);
            rd += (t[j] > t[e]) || (t[j] == t[e] && j < e);
        }
        g_gate[bt * HE + h * Ee + e] = (rs < KK) ? 1.0f / (1.0f + expf(-s[e])) : 0.f;
        g_sdg [bt * HE + h * Ee + e] = (rd < KK) ? 1.f : 0.f;
    }
}

// ---------------- expert V mix + transposed pack (gates precomputed) ---------
__global__ __launch_bounds__(256) void route_pack() {
    __shared__ uint32_t tvh[4][65];
    int gid = blockIdx.x * 256 + threadIdx.x;
    int d  = gid & 63;
    int kp = (gid >> 6) & 511;
    int bh = gid >> 15;
    int b = bh >> 3, h = bh & 7;

    float v[2];
#pragma unroll
    for (int u = 0; u < 2; u++) {
        int bt = b * 1024 + kp * 2 + u;
        const __half* vrow = (const __half*)g_Vf + (size_t)bt * V2 + h * Ee * 64 + d;
        const float* gz = g_gate + bt * HE + h * Ee;
        float acc = 0.f;
#pragma unroll
        for (int e = 0; e < Ee; e++)
            acc = fmaf(gz[e], __half2float(vrow[e * 64]), acc);
        v[u] = acc;
    }
    tvh[kp & 3][d] = packh2(v[0], v[1]);
    __syncthreads();
    int td  = threadIdx.x >> 2;
    int tk4 = threadIdx.x & 3;
    int kp0 = (blockIdx.x * 4) & 511;
    g_Vh[((size_t)bh * 64 + td) * 512 + kp0 + tk4] = tvh[tk4][td];
}

// ---------------- tensor-core causal flash attention (plain fp16) ------------
// S = Qh*Kh ; O += Ph*Vh.
#define AQS   (64 * 36)
#define ATL   (64 * 36)
#define ASTG  (2 * ATL)
#define AWG_U (AQS + 2 * ASTG)
#define ATTN_SMEM (2 * AWG_U * 4)

__global__ __launch_bounds__(256) void attn_tc() {
    extern __shared__ uint32_t sm[];
    const int bh   = blockIdx.y;
    const int b    = bh >> 3, h = bh & 7;
    const int wg   = threadIdx.x >> 7;
    const int qt   = wg ? (15 - blockIdx.x) : blockIdx.x;
    const int tid  = threadIdx.x & 127;
    const int w    = tid >> 5;
    const int lane = tid & 31;
    const int g    = lane >> 2;
    const int tig  = lane & 3;
    uint32_t* smg  = sm + wg * AWG_U;
    const uint32_t sb = smem_u32(smg);

    auto issue = [&](int kt, int s) {
#pragma unroll
        for (int i = 0; i < 8; i++) {
            int a = i >> 2;
            int r = (i & 3) * 16 + (tid >> 3);
            int c = tid & 7;
            uint32_t dst = sb + (AQS + s * ASTG + a * ATL + r * 36) * 4 + c * 16;
            const uint32_t* srcb;
            if (a == 0) srcb = g_Kh + ((size_t)(bh << 10) + kt * 64 + r) * 32;
            else        srcb = g_Vh + ((size_t)bh * 64 + r) * 512 + kt * 32;
            cpasync16(dst, (const char*)srcb + c * 16);
        }
    };
    issue(0, 0); cp_commit();

    {
        const uint32_t* qhsrc = g_Qh + ((size_t)(bh << 10) + qt * 64) * 32;
#pragma unroll
        for (int j = 0; j < 4; j++) {
            int idx = tid + j * 128;
            int row = idx >> 3, po = (idx & 7) * 4;
            *(uint4*)&smg[row * 36 + po] = *(const uint4*)(qhsrc + row * 32 + po);
        }
    }
    WGBAR(wg);

    uint32_t qa[4][4];
#pragma unroll
    for (int kb = 0; kb < 4; kb++) {
        qa[kb][0] = smg[(w * 16 + g)     * 36 + kb * 8 + tig];
        qa[kb][1] = smg[(w * 16 + g + 8) * 36 + kb * 8 + tig];
        qa[kb][2] = smg[(w * 16 + g)     * 36 + kb * 8 + 4 + tig];
        qa[kb][3] = smg[(w * 16 + g + 8) * 36 + kb * 8 + 4 + tig];
    }

    const int li   = lane >> 3;
    const uint32_t lbase = (((li >> 1) * 8 + (lane & 7)) * 36 + (li & 1) * 4) * 4;

    float o[8][4];
#pragma unroll
    for (int a = 0; a < 8; a++)
#pragma unroll
        for (int q = 0; q < 4; q++) o[a][q] = 0.f;
    float m[2] = {-1e30f, -1e30f}, l[2] = {0.f, 0.f};

    for (int kt = 0; kt <= qt; kt++) {
        if (kt < qt) { issue(kt + 1, (kt + 1) & 1); cp_commit(); cp_wait<1>(); }
        else         { cp_wait<0>(); }
        WGBAR(wg);

        const uint32_t su  = sb + (AQS + (kt & 1) * ASTG) * 4;
        const uint32_t Khb = su, Vhb = su + ATL * 4;

        float s[8][4];
#pragma unroll
        for (int a = 0; a < 8; a++)
#pragma unroll
            for (int q = 0; q < 4; q++) s[a][q] = 0.f;

#pragma unroll
        for (int kb = 0; kb < 4; kb++) {
            uint32_t bb[4][4];
#pragma unroll
            for (int j = 0; j < 4; j++)
                ldm_x4(bb[j], Khb + lbase + (j * 576 + kb * 8) * 4);
#pragma unroll
            for (int j = 0; j < 4; j++) {
                mma16816f(s[2*j],   qa[kb], &bb[j][0]);
                mma16816f(s[2*j+1], qa[kb], &bb[j][2]);
            }
        }

        if (kt == qt) {
            int r0 = w * 16 + g;
#pragma unroll
            for (int na = 0; na < 8; na++) {
                int c0 = na * 8 + 2 * tig;
                if (c0     > r0)     s[na][0] = -1e9f;
                if (c0 + 1 > r0)     s[na][1] = -1e9f;
                if (c0     > r0 + 8) s[na][2] = -1e9f;
                if (c0 + 1 > r0 + 8) s[na][3] = -1e9f;
            }
        }

#pragma unroll
        for (int ri = 0; ri < 2; ri++) {
            float mx = -1e30f;
#pragma unroll
            for (int a = 0; a < 8; a++)
                mx = fmaxf(mx, fmaxf(s[a][2 * ri], s[a][2 * ri + 1]));
            mx = fmaxf(mx, __shfl_xor_sync(0xffffffffu, mx, 1));
            mx = fmaxf(mx, __shfl_xor_sync(0xffffffffu, mx, 2));
            float mnew = fmaxf(m[ri], mx);
            float corr = __expf(m[ri] - mnew);
            float rs = 0.f;
#pragma unroll
            for (int a = 0; a < 8; a++) {
                float p0 = __expf(s[a][2 * ri]     - mnew);
                float p1 = __expf(s[a][2 * ri + 1] - mnew);
                s[a][2 * ri] = p0; s[a][2 * ri + 1] = p1;
                rs += p0 + p1;
            }
            rs += __shfl_xor_sync(0xffffffffu, rs, 1);
            rs += __shfl_xor_sync(0xffffffffu, rs, 2);
            l[ri] = l[ri] * corr + rs;
            m[ri] = mnew;
#pragma unroll
            for (int a = 0; a < 8; a++) { o[a][2 * ri] *= corr; o[a][2 * ri + 1] *= corr; }
        }

#pragma unroll
        for (int kb = 0; kb < 4; kb++) {
            uint32_t ph[4];
            ph[0] = packh2(s[2*kb][0],   s[2*kb][1]);
            ph[1] = packh2(s[2*kb][2],   s[2*kb][3]);
            ph[2] = packh2(s[2*kb+1][0], s[2*kb+1][1]);
            ph[3] = packh2(s[2*kb+1][2], s[2*kb+1][3]);

            uint32_t bb[4][4];
#pragma unroll
            for (int j = 0; j < 4; j++)
                ldm_x4(bb[j], Vhb + lbase + (j * 576 + kb * 8) * 4);
#pragma unroll
            for (int j = 0; j < 4; j++) {
                mma16816f(o[2*j],   ph, &bb[j][0]);
                mma16816f(o[2*j+1], ph, &bb[j][2]);
            }
        }
        WGBAR(wg);
    }

    // ---- fused epilogue: A2 = fp16(sd * O) for all 5 experts ----
    float inv0 = 1.0f / l[0], inv1 = 1.0f / l[1];
    int row0 = qt * 64 + w * 16 + g;
    int bt0  = b * 1024 + row0;

    float g0[Ee], g1[Ee];
#pragma unroll
    for (int e = 0; e < Ee; e++) {
        g0[e] = g_sdg[bt0 * HE + h * Ee + e];
        g1[e] = g_sdg[(bt0 + 8) * HE + h * Ee + e];
    }
    uint32_t* a2h0 = (uint32_t*)(g_W2 + A2H + (size_t)bt0 * V2);
    uint32_t* a2h1 = (uint32_t*)(g_W2 + A2H + (size_t)(bt0 + 8) * V2);

#pragma unroll
    for (int na = 0; na < 8; na++) {
        int c0 = na * 8 + 2 * tig;
        uint32_t h0u = packh2(o[na][0] * inv0, o[na][1] * inv0);
        uint32_t h1u = packh2(o[na][2] * inv1, o[na][3] * inv1);
#pragma unroll
        for (int e = 0; e < Ee; e++) {
            int cw = ((h * Ee + e) * 64 + c0) >> 1;
            a2h0[cw] = (g0[e] != 0.f) ? h0u : 0u;
            a2h1[cw] = (g1[e] != 0.f) ? h1u : 0u;
        }
    }
}

// ---------------- launch ------------------------------------------------------
extern "C" void kernel_launch(void* const* d_in, const int* in_sizes, int n_in,
                              void* d_out, int out_size)
{
    const float* x  = (const float*)d_in[0];
    const float* Wq = (const float*)d_in[1];
    const float* Wk = (const float*)d_in[2];
    const float* Wv = (const float*)d_in[3];
    const float* Ws = (const float*)d_in[4];
    const float* Wd = (const float*)d_in[5];
    const float* Wo = (const float*)d_in[6];
    float* out = (float*)d_out;

    cudaFuncSetAttribute(gemm1,   cudaFuncAttributeMaxDynamicSharedMemorySize, GEMM1_SMEM);
    cudaFuncSetAttribute(gemm2,   cudaFuncAttributeMaxDynamicSharedMemorySize, GEMM2_SMEM);
    cudaFuncSetAttribute(attn_tc, cudaFuncAttributeMaxDynamicSharedMemorySize, ATTN_SMEM);

    prep_misc <<<8192 + 10240, 256>>>(x, Wo);
    prep_b1   <<<dim3(32, 120), dim3(32, 8)>>>(Wq, Wk, Wv, Ws, Wd);
    gemm1     <<<dim3(58, 16), 256, GEMM1_SMEM>>>();
    gates_k   <<<BT * Hh / 256, 256>>>();
    route_pack<<<16 * 512 * 64 / 256, 256>>>();
    attn_tc   <<<dim3(8, 16), 256, ATTN_SMEM>>>();
    gemm2     <<<dim3(N2 / 64, BT / 128), 256, GEMM2_SMEM>>>(out);
}

// round 17
// speedup vs baseline: 1.6177x; 1.0528x over previous
#include <cuda_runtime.h>
#include <cuda_fp16.h>
#include <cstdint>

#define Tt   1024
#define DIMD 1024
#define Hh   8
#define Ee   5
#define KK   3
#define BT   2048
#define HS   512
#define HE   40
#define QSCALE 0.125f

#define N1 3840
#define N2 1024
#define V2 2560

// ---------------- scratch ----------------------------------------------------
__device__ float g_C1 [BT * N1];          // only SsSd cols (3584+) used
__device__ __half g_Vf[(size_t)BT * V2];  // V projection output, fp16
#define A1Hf 0
#define A1Lf (BT * 1024)
#define B1Hf (2 * BT * 1024)
#define B1Lf (2 * BT * 1024 + N1 * 1024)
__device__ __half g_W1f[2 * BT * 1024 + 2 * N1 * 1024];
#define A2H 0
#define B2H (BT * V2)
__device__ __half g_W2[BT * V2 + N2 * V2];

__device__ float g_sdg [BT * HE];   // 0/1 dest gates
// attention operands: packed fp16x2 pairs (single-rounded fp16)
__device__ uint32_t g_Qh[16 * 1024 * 32];   // [bh][t][dpair]
__device__ uint32_t g_Kh[16 * 1024 * 32];
__device__ uint32_t g_Vh[16 * 64 * 512];    // [bh][d][tpair]

// ---------------- helpers -----------------------------------------------------
__device__ __forceinline__ uint32_t smem_u32(const void* p) {
    uint32_t a;
    asm("{ .reg .u64 t; cvta.to.shared.u64 t, %1; cvt.u32.u64 %0, t; }" : "=r"(a) : "l"(p));
    return a;
}
__device__ __forceinline__ void cpasync16(uint32_t dst, const void* src) {
    asm volatile("cp.async.cg.shared.global [%0], [%1], 16;\n" :: "r"(dst), "l"(src));
}
__device__ __forceinline__ void cp_commit() { asm volatile("cp.async.commit_group;\n"); }
template<int N> __device__ __forceinline__ void cp_wait() { asm volatile("cp.async.wait_group %0;\n" :: "n"(N)); }

__device__ __forceinline__ void mma16816f(float* c, const uint32_t* a, const uint32_t* b) {
    asm volatile(
        "mma.sync.aligned.m16n8k16.row.col.f32.f16.f16.f32 "
        "{%0,%1,%2,%3}, {%4,%5,%6,%7}, {%8,%9}, {%0,%1,%2,%3};"
        : "+f"(c[0]), "+f"(c[1]), "+f"(c[2]), "+f"(c[3])
        : "r"(a[0]), "r"(a[1]), "r"(a[2]), "r"(a[3]), "r"(b[0]), "r"(b[1]));
}
__device__ __forceinline__ void ldm_x4(uint32_t* r, uint32_t addr) {
    asm volatile("ldmatrix.sync.aligned.m8n8.x4.shared.b16 {%0,%1,%2,%3}, [%4];"
        : "=r"(r[0]), "=r"(r[1]), "=r"(r[2]), "=r"(r[3]) : "r"(addr));
}
__device__ __forceinline__ uint32_t packh2(float lo, float hi) {
    __half2 h = __floats2half2_rn(lo, hi);
    return *(uint32_t*)&h;
}
__device__ __forceinline__ uint32_t packh2res(uint32_t p, float lo, float hi) {
    __half2 ph = *(__half2*)&p;
    float2 bk = __half22float2(ph);
    return packh2(lo - bk.x, hi - bk.y);
}
#define WGBAR(id) asm volatile("bar.sync %0, 128;" :: "r"((id) + 1) : "memory")

// ---------------- fp16 GEMM (gemm1), BK=32, configurable split terms ---------
template<int NT, int KTOT, bool FUSEQK, bool VOUT, bool ASPLIT, bool BSPLIT>
__device__ __forceinline__ void gemmf_body(const char* __restrict__ W,
                                           uint32_t offAh, uint32_t offAl,
                                           uint32_t offBh, uint32_t offBl,
                                           float* __restrict__ C, int Ntot)
{
    constexpr int AR    = ASPLIT ? 256 : 128;
    constexpr int AC    = ASPLIT ? 4 : 2;
    constexpr int ROWS  = AR + (BSPLIT ? 2 : 1) * NT;
    constexpr int STAGE = ROWS * 64;
    constexpr int NSTEP = KTOT / 32;
    constexpr int NTW   = NT / 2;
    constexpr int NPAIR = NTW / 16;
    constexpr int NA    = NTW / 8;
    constexpr int CPT   = ROWS / 64;
    constexpr int NB    = NT / 64;
    constexpr size_t K2B = KTOT * 2;

    extern __shared__ char sm_raw[];
    const uint32_t sb = smem_u32(sm_raw);
    const int tid = threadIdx.x, wid = tid >> 5, lane = tid & 31;
    const int wm = wid & 3, wn = wid >> 2;
    const int m0 = blockIdx.y * 128, n0 = blockIdx.x * NT;

    const int r0 = tid >> 2;
    const int cc = (tid & 3) * 16;
    const uint32_t dst0 = r0 * 64 + (cc ^ (((r0 >> 1) & 3) * 16));
    const char* pAh = W + offAh + (size_t)(m0 + r0) * K2B + cc;
    const char* pAl = W + offAl + (size_t)(m0 + r0) * K2B + cc;
    const char* pBh = W + offBh + (size_t)(n0 + r0) * K2B + cc;
    const char* pBl = W + offBl + (size_t)(n0 + r0) * K2B + cc;

    auto issue = [&](int kt, int slot) {
        const uint32_t st = sb + slot * STAGE + dst0;
        const size_t gk = (size_t)kt * 64;
#pragma unroll
        for (int i = 0; i < CPT; i++) {
            const char* src;
            if      (i < 2)            src = pAh + (size_t)i * (64 * K2B);
            else if (ASPLIT && i < AC) src = pAl + (size_t)(i - 2) * (64 * K2B);
            else if (i < AC + NB)      src = pBh + (size_t)(i - AC) * (64 * K2B);
            else                       src = pBl + (size_t)(i - AC - NB) * (64 * K2B);
            cpasync16(st + i * 4096, src + gk);
        }
    };

    const uint32_t ahi = (lane >> 4) * 16;
    const uint32_t bhi = ((lane >> 3) & 1) * 16;
    uint32_t aof[2], aswz[2], bof[NPAIR], bswz[NPAIR];
#pragma unroll
    for (int mi = 0; mi < 2; mi++) {
        int r = wm * 32 + mi * 16 + (lane & 15);
        aof[mi] = r * 64; aswz[mi] = ((r >> 1) & 3) * 16;
    }
#pragma unroll
    for (int pj = 0; pj < NPAIR; pj++) {
        int r = wn * NTW + pj * 16 + ((lane >> 4) << 3) + (lane & 7);
        bof[pj] = (AR + r) * 64; bswz[pj] = ((r >> 1) & 3) * 16;
    }

    float acc[2][NA][4];
#pragma unroll
    for (int mi = 0; mi < 2; mi++)
#pragma unroll
        for (int na = 0; na < NA; na++)
#pragma unroll
            for (int q = 0; q < 4; q++) acc[mi][na][q] = 0.f;

    issue(0, 0); cp_commit();
    issue(1, 1); cp_commit();

    for (int kt = 0; kt < NSTEP; kt++) {
        if (kt + 1 < NSTEP) cp_wait<1>(); else cp_wait<0>();
        __syncthreads();
        if (kt + 2 < NSTEP) { issue(kt + 2, (kt + 2) % 3); cp_commit(); }

        uint32_t stg = sb + (kt % 3) * STAGE;
#pragma unroll
        for (int ks = 0; ks < 2; ks++) {
            const uint32_t ca = (uint32_t)ks * 32 + ahi;
            const uint32_t cb = (uint32_t)ks * 32 + bhi;
            uint32_t ah[2][4], al[2][4], bb[NPAIR][4];
            ldm_x4(ah[0], stg + aof[0] + (ca ^ aswz[0]));
            ldm_x4(ah[1], stg + aof[1] + (ca ^ aswz[1]));
            if (ASPLIT) {
                ldm_x4(al[0], stg + 8192 + aof[0] + (ca ^ aswz[0]));
                ldm_x4(al[1], stg + 8192 + aof[1] + (ca ^ aswz[1]));
            }
#pragma unroll
            for (int pj = 0; pj < NPAIR; pj++)
                ldm_x4(bb[pj], stg + bof[pj] + (cb ^ bswz[pj]));
#pragma unroll
            for (int mi = 0; mi < 2; mi++)
#pragma unroll
                for (int pj = 0; pj < NPAIR; pj++) {
                    mma16816f(acc[mi][2 * pj],     ah[mi], &bb[pj][0]);
                    mma16816f(acc[mi][2 * pj + 1], ah[mi], &bb[pj][2]);
                }
            if (ASPLIT) {
#pragma unroll
                for (int mi = 0; mi < 2; mi++)
#pragma unroll
                    for (int pj = 0; pj < NPAIR; pj++) {
                        mma16816f(acc[mi][2 * pj],     al[mi], &bb[pj][0]);
                        mma16816f(acc[mi][2 * pj + 1], al[mi], &bb[pj][2]);
                    }
            }
            if (BSPLIT) {
#pragma unroll
                for (int pj = 0; pj < NPAIR; pj++)
                    ldm_x4(bb[pj], stg + bof[pj] + NT * 64 + (cb ^ bswz[pj]));
#pragma unroll
                for (int mi = 0; mi < 2; mi++)
#pragma unroll
                    for (int pj = 0; pj < NPAIR; pj++) {
                        mma16816f(acc[mi][2 * pj],     ah[mi], &bb[pj][0]);
                        mma16816f(acc[mi][2 * pj + 1], ah[mi], &bb[pj][2]);
                    }
            }
        }
    }

    const int g  = lane >> 2;
    const int tg = lane & 3;

    if (FUSEQK && n0 < 1024) {
        const bool isQ = (n0 < 512);
        const float sc = isQ ? QSCALE : 1.0f;
        uint32_t* dh = isQ ? g_Qh : g_Kh;
#pragma unroll
        for (int mi = 0; mi < 2; mi++) {
            int r = m0 + wm * 32 + mi * 16 + g;
            int b_ = r >> 10, t = r & 1023;
#pragma unroll
            for (int na = 0; na < NA; na++) {
                int ccc = n0 + wn * NTW + na * 8 + tg * 2;
                int h = (ccc >> 6) & 7;
                int p = (ccc & 63) >> 1;
                size_t base = (((size_t)(b_ * 8 + h) << 10) + t) * 32 + p;
                dh[base]          = packh2(acc[mi][na][0] * sc, acc[mi][na][1] * sc);
                dh[base + 8 * 32] = packh2(acc[mi][na][2] * sc, acc[mi][na][3] * sc);
            }
        }
    } else if (VOUT) {
#pragma unroll
        for (int mi = 0; mi < 2; mi++) {
            int r = m0 + wm * 32 + mi * 16 + g;
#pragma unroll
            for (int na = 0; na < NA; na++) {
                int vc = n0 - 1024 + wn * NTW + na * 8 + tg * 2;
                *(uint32_t*)((__half*)g_Vf + (size_t)r * V2 + vc) =
                    packh2(acc[mi][na][0], acc[mi][na][1]);
                *(uint32_t*)((__half*)g_Vf + (size_t)(r + 8) * V2 + vc) =
                    packh2(acc[mi][na][2], acc[mi][na][3]);
            }
        }
    } else {
#pragma unroll
        for (int mi = 0; mi < 2; mi++) {
            int r = m0 + wm * 32 + mi * 16 + g;
#pragma unroll
            for (int na = 0; na < NA; na++) {
                int ccc = n0 + wn * NTW + na * 8 + tg * 2;
                *(float2*)(C + (size_t)r * Ntot + ccc)       = make_float2(acc[mi][na][0], acc[mi][na][1]);
                *(float2*)(C + (size_t)(r + 8) * Ntot + ccc) = make_float2(acc[mi][na][2], acc[mi][na][3]);
            }
        }
    }
}

#define GEMM1_SMEM (3 * (256 + 128) * 64)   // 73728

__global__ __launch_bounds__(256, 3)
void gemm1() {
    if (blockIdx.x < 16)
        gemmf_body<64, 1024, true,  false, true,  false>((const char*)g_W1f, A1Hf*2, A1Lf*2, B1Hf*2, B1Lf*2, g_C1, N1);
    else if (blockIdx.x < 56)
        gemmf_body<64, 1024, false, true,  false, false>((const char*)g_W1f, A1Hf*2, A1Lf*2, B1Hf*2, B1Lf*2, g_C1, N1);
    else
        gemmf_body<64, 1024, false, false, true,  true >((const char*)g_W1f, A1Hf*2, A1Lf*2, B1Hf*2, B1Lf*2, g_C1, N1);
}

// ---------------- gemm2: plain fp16 1-term, BK=64, 128B smem rows ------------
#define GEMM2_SMEM (3 * 192 * 128)   // 73728

__global__ __launch_bounds__(256, 3)
void gemm2(float* __restrict__ out) {
    constexpr int KTOT  = V2;            // 2560
    constexpr int NSTEP = KTOT / 64;     // 40
    constexpr int STAGE = 192 * 128;
    constexpr size_t K2B = KTOT * 2;

    extern __shared__ char sm_raw[];
    const uint32_t sb = smem_u32(sm_raw);
    const int tid = threadIdx.x, wid = tid >> 5, lane = tid & 31;
    const int wm = wid & 3, wn = wid >> 2;
    const int m0 = blockIdx.y * 128, n0 = blockIdx.x * 64;

    const char* W = (const char*)g_W2;
    const int r0 = tid >> 3;             // 0..31
    const int cc = (tid & 7) * 16;
    const uint32_t dst0 = r0 * 128 + (cc ^ ((r0 & 7) * 16));
    const char* pA = W + (size_t)(A2H * 2) + (size_t)(m0 + r0) * K2B + cc;
    const char* pB = W + (size_t)(B2H * 2) + (size_t)(n0 + r0) * K2B + cc;

    auto issue = [&](int kt, int slot) {
        const uint32_t st = sb + slot * STAGE + dst0;
        const size_t gk = (size_t)kt * 128;
#pragma unroll
        for (int i = 0; i < 6; i++) {
            const char* src = (i < 4) ? pA + (size_t)i * (32 * K2B)
                                      : pB + (size_t)(i - 4) * (32 * K2B);
            cpasync16(st + i * 4096, src + gk);
        }
    };

    const uint32_t ahi = (lane >> 4) * 16;
    const uint32_t bhi = ((lane >> 3) & 1) * 16;
    uint32_t aof[2], aswz[2], bof[2], bswz[2];
#pragma unroll
    for (int mi = 0; mi < 2; mi++) {
        int r = wm * 32 + mi * 16 + (lane & 15);
        aof[mi] = r * 128; aswz[mi] = (r & 7) * 16;
    }
#pragma unroll
    for (int pj = 0; pj < 2; pj++) {
        int r = wn * 32 + pj * 16 + ((lane >> 4) << 3) + (lane & 7);
        bof[pj] = (128 + r) * 128; bswz[pj] = (r & 7) * 16;
    }

    float acc[2][4][4];
#pragma unroll
    for (int mi = 0; mi < 2; mi++)
#pragma unroll
        for (int na = 0; na < 4; na++)
#pragma unroll
            for (int q = 0; q < 4; q++) acc[mi][na][q] = 0.f;

    issue(0, 0); cp_commit();
    issue(1, 1); cp_commit();

    for (int kt = 0; kt < NSTEP; kt++) {
        if (kt + 1 < NSTEP) cp_wait<1>(); else cp_wait<0>();
        __syncthreads();
        if (kt + 2 < NSTEP) { issue(kt + 2, (kt + 2) % 3); cp_commit(); }

        uint32_t stg = sb + (kt % 3) * STAGE;
#pragma unroll
        for (int ks = 0; ks < 4; ks++) {
            const uint32_t ca = (uint32_t)ks * 32 + ahi;
            const uint32_t cb = (uint32_t)ks * 32 + bhi;
            uint32_t ah[2][4], bb[2][4];
            ldm_x4(ah[0], stg + aof[0] + (ca ^ aswz[0]));
            ldm_x4(ah[1], stg + aof[1] + (ca ^ aswz[1]));
            ldm_x4(bb[0], stg + bof[0] + (cb ^ bswz[0]));
            ldm_x4(bb[1], stg + bof[1] + (cb ^ bswz[1]));
#pragma unroll
            for (int mi = 0; mi < 2; mi++)
#pragma unroll
                for (int pj = 0; pj < 2; pj++) {
                    mma16816f(acc[mi][2 * pj],     ah[mi], &bb[pj][0]);
                    mma16816f(acc[mi][2 * pj + 1], ah[mi], &bb[pj][2]);
                }
        }
    }

    const int g  = lane >> 2;
    const int tg = lane & 3;
#pragma unroll
    for (int mi = 0; mi < 2; mi++) {
        int r = m0 + wm * 32 + mi * 16 + g;
#pragma unroll
        for (int na = 0; na < 4; na++) {
            int ccc = n0 + wn * 32 + na * 8 + tg * 2;
            *(float2*)(out + (size_t)r * N2 + ccc)       = make_float2(acc[mi][na][0], acc[mi][na][1]);
            *(float2*)(out + (size_t)(r + 8) * N2 + ccc) = make_float2(acc[mi][na][2], acc[mi][na][3]);
        }
    }
}

// ---------------- merged prep kernel -----------------------------------------
// blocks [0,8192): x split; [8192,18432): Wo pack; [18432,22272): W1 transpose
__global__ __launch_bounds__(256) void prep_all(const float* __restrict__ x,
                                                const float* __restrict__ Wo,
                                                const float* __restrict__ Wq,
                                                const float* __restrict__ Wk,
                                                const float* __restrict__ Wv,
                                                const float* __restrict__ Ws,
                                                const float* __restrict__ Wd) {
    int bid = blockIdx.x;
    if (bid < 8192) {
        int gid = bid * 256 + threadIdx.x;
        float v = x[gid];
        __half fh = __float2half_rn(v);
        __half fl = __float2half_rn(v - __half2float(fh));
        g_W1f[A1Hf + gid] = fh;
        g_W1f[A1Lf + gid] = fl;
    } else if (bid < 18432) {
        int gid = (bid - 8192) * 256 + threadIdx.x;
        int he = gid >> 16;
        int d  = (gid >> 6) & 1023;
        int c  = gid & 63;
        g_W2[B2H + d * V2 + he * 64 + c] = __float2half_rn(Wo[gid]);
    } else {
        __shared__ float tile[32][33];
        int bid2 = bid - 18432;
        int k0 = (bid2 & 31) * 32;
        int n0 = (bid2 >> 5) * 32;
        int tx = threadIdx.x & 31, ty = threadIdx.x >> 5;
#pragma unroll
        for (int yy = 0; yy < 32; yy += 8) {
            int k = k0 + ty + yy, n = n0 + tx;
            float w;
            if      (n < 512)  w = Wq[(size_t)k * 512  + n];
            else if (n < 1024) w = Wk[(size_t)k * 512  + n - 512];
            else if (n < 3584) w = Wv[(size_t)k * 2560 + n - 1024];
            else if (n < 3624) w = Ws[(size_t)k * 40   + n - 3584];
            else if (n < 3664) w = Wd[(size_t)k * 40   + n - 3624];
            else               w = 0.f;
            tile[ty + yy][tx] = w;
        }
        __syncthreads();
#pragma unroll
        for (int yy = 0; yy < 32; yy += 8) {
            int n = n0 + ty + yy, k = k0 + tx;
            float w = tile[tx][ty + yy];
            int idx = n * 1024 + k;
            __half fh = __float2half_rn(w);
            g_W1f[B1Hf + idx] = fh;
            if (n >= 3584)
                g_W1f[B1Lf + idx] = __float2half_rn(w - __half2float(fh));
        }
    }
}

// ---------------- route_pack with fused gates --------------------------------
// Block covers one bh and 8 consecutive bt (kp0*2 .. kp0*2+7).
__global__ __launch_bounds__(256) void route_pack() {
    __shared__ uint32_t tvh[4][65];
    __shared__ float sgate[8][Ee];
    int tid = threadIdx.x;
    int bh  = blockIdx.x >> 7;
    int kp0 = (blockIdx.x * 4) & 511;
    int b = bh >> 3, h = bh & 7;

    // 40 threads compute source gates (smem) + dest gates (global, each once)
    if (tid < 8 * Ee) {
        int btl = tid / Ee, e = tid % Ee;
        int bt = b * 1024 + kp0 * 2 + btl;
        const float* row = g_C1 + (size_t)bt * N1;
        const float* sl = row + 3584 + h * Ee;
        const float* dl = row + 3624 + h * Ee;
        float s[Ee], t[Ee];
#pragma unroll
        for (int j = 0; j < Ee; j++) { s[j] = sl[j]; t[j] = dl[j]; }
        int rs = 0, rd = 0;
#pragma unroll
        for (int j = 0; j < Ee; j++) {
            rs += (s[j] > s[e]) || (s[j] == s[e] && j < e);
            rd += (t[j] > t[e]) || (t[j] == t[e] && j < e);
        }
        sgate[btl][e] = (rs < KK) ? 1.0f / (1.0f + expf(-s[e])) : 0.f;
        g_sdg[bt * HE + h * Ee + e] = (rd < KK) ? 1.f : 0.f;
    }
    __syncthreads();

    int d  = tid & 63;
    int kpl = tid >> 6;                 // 0..3 local kp
    float v[2];
#pragma unroll
    for (int u = 0; u < 2; u++) {
        int btl = kpl * 2 + u;
        int bt  = b * 1024 + kp0 * 2 + btl;
        const __half* vrow = (const __half*)g_Vf + (size_t)bt * V2 + h * Ee * 64 + d;
        float acc = 0.f;
#pragma unroll
        for (int e = 0; e < Ee; e++)
            acc = fmaf(sgate[btl][e], __half2float(vrow[e * 64]), acc);
        v[u] = acc;
    }
    tvh[kpl][d] = packh2(v[0], v[1]);
    __syncthreads();
    int td  = tid >> 2;
    int tk4 = tid & 3;
    g_Vh[((size_t)bh * 64 + td) * 512 + kp0 + tk4] = tvh[tk4][td];
}

// ---------------- tensor-core causal flash attention (plain fp16) ------------
#define AQS   (64 * 36)
#define ATL   (64 * 36)
#define ASTG  (2 * ATL)
#define AWG_U (AQS + 2 * ASTG)
#define ATTN_SMEM (2 * AWG_U * 4)

__global__ __launch_bounds__(256) void attn_tc() {
    extern __shared__ uint32_t sm[];
    const int bh   = blockIdx.y;
    const int b    = bh >> 3, h = bh & 7;
    const int wg   = threadIdx.x >> 7;
    const int qt   = wg ? (15 - blockIdx.x) : blockIdx.x;
    const int tid  = threadIdx.x & 127;
    const int w    = tid >> 5;
    const int lane = tid & 31;
    const int g    = lane >> 2;
    const int tig  = lane & 3;
    uint32_t* smg  = sm + wg * AWG_U;
    const uint32_t sb = smem_u32(smg);

    auto issue = [&](int kt, int s) {
#pragma unroll
        for (int i = 0; i < 8; i++) {
            int a = i >> 2;
            int r = (i & 3) * 16 + (tid >> 3);
            int c = tid & 7;
            uint32_t dst = sb + (AQS + s * ASTG + a * ATL + r * 36) * 4 + c * 16;
            const uint32_t* srcb;
            if (a == 0) srcb = g_Kh + ((size_t)(bh << 10) + kt * 64 + r) * 32;
            else        srcb = g_Vh + ((size_t)bh * 64 + r) * 512 + kt * 32;
            cpasync16(dst, (const char*)srcb + c * 16);
        }
    };
    issue(0, 0); cp_commit();

    {
        const uint32_t* qhsrc = g_Qh + ((size_t)(bh << 10) + qt * 64) * 32;
#pragma unroll
        for (int j = 0; j < 4; j++) {
            int idx = tid + j * 128;
            int row = idx >> 3, po = (idx & 7) * 4;
            *(uint4*)&smg[row * 36 + po] = *(const uint4*)(qhsrc + row * 32 + po);
        }
    }
    WGBAR(wg);

    uint32_t qa[4][4];
#pragma unroll
    for (int kb = 0; kb < 4; kb++) {
        qa[kb][0] = smg[(w * 16 + g)     * 36 + kb * 8 + tig];
        qa[kb][1] = smg[(w * 16 + g + 8) * 36 + kb * 8 + tig];
        qa[kb][2] = smg[(w * 16 + g)     * 36 + kb * 8 + 4 + tig];
        qa[kb][3] = smg[(w * 16 + g + 8) * 36 + kb * 8 + 4 + tig];
    }

    const int li   = lane >> 3;
    const uint32_t lbase = (((li >> 1) * 8 + (lane & 7)) * 36 + (li & 1) * 4) * 4;

    float o[8][4];
#pragma unroll
    for (int a = 0; a < 8; a++)
#pragma unroll
        for (int q = 0; q < 4; q++) o[a][q] = 0.f;
    float m[2] = {-1e30f, -1e30f}, l[2] = {0.f, 0.f};

    for (int kt = 0; kt <= qt; kt++) {
        if (kt < qt) { issue(kt + 1, (kt + 1) & 1); cp_commit(); cp_wait<1>(); }
        else         { cp_wait<0>(); }
        WGBAR(wg);

        const uint32_t su  = sb + (AQS + (kt & 1) * ASTG) * 4;
        const uint32_t Khb = su, Vhb = su + ATL * 4;

        float s[8][4];
#pragma unroll
        for (int a = 0; a < 8; a++)
#pragma unroll
            for (int q = 0; q < 4; q++) s[a][q] = 0.f;

#pragma unroll
        for (int kb = 0; kb < 4; kb++) {
            uint32_t bb[4][4];
#pragma unroll
            for (int j = 0; j < 4; j++)
                ldm_x4(bb[j], Khb + lbase + (j * 576 + kb * 8) * 4);
#pragma unroll
            for (int j = 0; j < 4; j++) {
                mma16816f(s[2*j],   qa[kb], &bb[j][0]);
                mma16816f(s[2*j+1], qa[kb], &bb[j][2]);
            }
        }

        if (kt == qt) {
            int r0 = w * 16 + g;
#pragma unroll
            for (int na = 0; na < 8; na++) {
                int c0 = na * 8 + 2 * tig;
                if (c0     > r0)     s[na][0] = -1e9f;
                if (c0 + 1 > r0)     s[na][1] = -1e9f;
                if (c0     > r0 + 8) s[na][2] = -1e9f;
                if (c0 + 1 > r0 + 8) s[na][3] = -1e9f;
            }
        }

#pragma unroll
        for (int ri = 0; ri < 2; ri++) {
            float mx = -1e30f;
#pragma unroll
            for (int a = 0; a < 8; a++)
                mx = fmaxf(mx, fmaxf(s[a][2 * ri], s[a][2 * ri + 1]));
            mx = fmaxf(mx, __shfl_xor_sync(0xffffffffu, mx, 1));
            mx = fmaxf(mx, __shfl_xor_sync(0xffffffffu, mx, 2));
            float mnew = fmaxf(m[ri], mx);
            float corr = __expf(m[ri] - mnew);
            float rs = 0.f;
#pragma unroll
            for (int a = 0; a < 8; a++) {
                float p0 = __expf(s[a][2 * ri]     - mnew);
                float p1 = __expf(s[a][2 * ri + 1] - mnew);
                s[a][2 * ri] = p0; s[a][2 * ri + 1] = p1;
                rs += p0 + p1;
            }
            rs += __shfl_xor_sync(0xffffffffu, rs, 1);
            rs += __shfl_xor_sync(0xffffffffu, rs, 2);
            l[ri] = l[ri] * corr + rs;
            m[ri] = mnew;
#pragma unroll
            for (int a = 0; a < 8; a++) { o[a][2 * ri] *= corr; o[a][2 * ri + 1] *= corr; }
        }

#pragma unroll
        for (int kb = 0; kb < 4; kb++) {
            uint32_t ph[4];
            ph[0] = packh2(s[2*kb][0],   s[2*kb][1]);
            ph[1] = packh2(s[2*kb][2],   s[2*kb][3]);
            ph[2] = packh2(s[2*kb+1][0], s[2*kb+1][1]);
            ph[3] = packh2(s[2*kb+1][2], s[2*kb+1][3]);

            uint32_t bb[4][4];
#pragma unroll
            for (int j = 0; j < 4; j++)
                ldm_x4(bb[j], Vhb + lbase + (j * 576 + kb * 8) * 4);
#pragma unroll
            for (int j = 0; j < 4; j++) {
                mma16816f(o[2*j],   ph, &bb[j][0]);
                mma16816f(o[2*j+1], ph, &bb[j][2]);
            }
        }
        WGBAR(wg);
    }

    // ---- fused epilogue: A2 = fp16(sd * O) for all 5 experts ----
    float inv0 = 1.0f / l[0], inv1 = 1.0f / l[1];
    int row0 = qt * 64 + w * 16 + g;
    int bt0  = b * 1024 + row0;

    float g0[Ee], g1[Ee];
#pragma unroll
    for (int e = 0; e < Ee; e++) {
        g0[e] = g_sdg[bt0 * HE + h * Ee + e];
        g1[e] = g_sdg[(bt0 + 8) * HE + h * Ee + e];
    }
    uint32_t* a2h0 = (uint32_t*)(g_W2 + A2H + (size_t)bt0 * V2);
    uint32_t* a2h1 = (uint32_t*)(g_W2 + A2H + (size_t)(bt0 + 8) * V2);

#pragma unroll
    for (int na = 0; na < 8; na++) {
        int c0 = na * 8 + 2 * tig;
        uint32_t h0u = packh2(o[na][0] * inv0, o[na][1] * inv0);
        uint32_t h1u = packh2(o[na][2] * inv1, o[na][3] * inv1);
#pragma unroll
        for (int e = 0; e < Ee; e++) {
            int cw = ((h * Ee + e) * 64 + c0) >> 1;
            a2h0[cw] = (g0[e] != 0.f) ? h0u : 0u;
            a2h1[cw] = (g1[e] != 0.f) ? h1u : 0u;
        }
    }
}

// ---------------- launch ------------------------------------------------------
extern "C" void kernel_launch(void* const* d_in, const int* in_sizes, int n_in,
                              void* d_out, int out_size)
{
    const float* x  = (const float*)d_in[0];
    const float* Wq = (const float*)d_in[1];
    const float* Wk = (const float*)d_in[2];
    const float* Wv = (const float*)d_in[3];
    const float* Ws = (const float*)d_in[4];
    const float* Wd = (const float*)d_in[5];
    const float* Wo = (const float*)d_in[6];
    float* out = (float*)d_out;

    cudaFuncSetAttribute(gemm1,   cudaFuncAttributeMaxDynamicSharedMemorySize, GEMM1_SMEM);
    cudaFuncSetAttribute(gemm2,   cudaFuncAttributeMaxDynamicSharedMemorySize, GEMM2_SMEM);
    cudaFuncSetAttribute(attn_tc, cudaFuncAttributeMaxDynamicSharedMemorySize, ATTN_SMEM);

    prep_all  <<<22272, 256>>>(x, Wo, Wq, Wk, Wv, Ws, Wd);
    gemm1     <<<dim3(58, 16), 256, GEMM1_SMEM>>>();
    route_pack<<<16 * 512 * 64 / 256, 256>>>();
    attn_tc   <<<dim3(8, 16), 256, ATTN_SMEM>>>();
    gemm2     <<<dim3(N2 / 64, BT / 128), 256, GEMM2_SMEM>>>(out);
}